// round 8
// baseline (speedup 1.0000x reference)
#include <cuda_runtime.h>
#include <cstdint>

#define BB  4
#define NN  16384
#define SS  4096
#define KK  32
#define CINF 16
#define C0  19
#define C1  32
#define C2  32
#define C3  64
#define EPSF 1e-5f

// spatial grid
#define GG     32
#define NC     (GG * GG * GG)
#define BOUNDF 4.5f
#define HH     (9.0f / (float)GG)
#define MARGIN 1e-3f

// ---------------- scratch (no allocs allowed) ----------------
__device__ int    g_knn[BB * SS * KK];
__device__ float  g_a1[C1], g_b1[C1];
__device__ float  g_a2[C2], g_b2[C2];
__device__ float  g_a3[C3], g_b3[C3];

__device__ float4 g_pts[BB * NN];        // cell-sorted (x, y, z, ||p||^2)
__device__ int    g_pidx[BB * NN];       // in-batch original index
__device__ int    g_cell[BB * NN];       // cell id per original point
__device__ int    g_cnt[BB * NC];
__device__ int    g_cstart[BB * NC + 1];
__device__ int    g_ccur[BB * NC];

// ---------------- prep: fold BN as post-affine ----------------
__global__ void prep_kernel(
    const float* __restrict__ b0,
    const float* __restrict__ g0, const float* __restrict__ bt0,
    const float* __restrict__ rm0, const float* __restrict__ rv0,
    const float* __restrict__ b1,
    const float* __restrict__ g1, const float* __restrict__ bt1,
    const float* __restrict__ rm1, const float* __restrict__ rv1,
    const float* __restrict__ b2,
    const float* __restrict__ g2, const float* __restrict__ bt2,
    const float* __restrict__ rm2, const float* __restrict__ rv2)
{
    int t = threadIdx.x;
    if (t < C1) {
        float A = g0[t] * rsqrtf(rv0[t] + EPSF);
        g_a1[t] = A;
        g_b1[t] = (b0[t] - rm0[t]) * A + bt0[t];
    }
    if (t < C2) {
        float A = g1[t] * rsqrtf(rv1[t] + EPSF);
        g_a2[t] = A;
        g_b2[t] = (b1[t] - rm1[t]) * A + bt1[t];
    }
    if (t < C3) {
        float A = g2[t] * rsqrtf(rv2[t] + EPSF);
        g_a3[t] = A;
        g_b3[t] = (b2[t] - rm2[t]) * A + bt2[t];
    }
}

// ---------------- binning ----------------
__global__ void zero_kernel()
{
    int i = blockIdx.x * blockDim.x + threadIdx.x;
    if (i < BB * NC) g_cnt[i] = 0;
}

__device__ __forceinline__ int cell_of(float x, float y, float z)
{
    int cx = (int)floorf((x + BOUNDF) * (1.0f / HH));
    int cy = (int)floorf((y + BOUNDF) * (1.0f / HH));
    int cz = (int)floorf((z + BOUNDF) * (1.0f / HH));
    cx = min(GG - 1, max(0, cx));
    cy = min(GG - 1, max(0, cy));
    cz = min(GG - 1, max(0, cz));
    return (cx * GG + cy) * GG + cz;
}

__global__ void count_kernel(const float* __restrict__ xyz)
{
    int i = blockIdx.x * blockDim.x + threadIdx.x;
    if (i >= BB * NN) return;
    int b = i >> 14;
    const float* p = xyz + (size_t)i * 3;
    int cell = cell_of(p[0], p[1], p[2]);
    g_cell[i] = cell;
    atomicAdd(&g_cnt[b * NC + cell], 1);
}

__global__ void scan_kernel()   // grid = BB, block = 1024; 32 cells/thread
{
    __shared__ int sm[1024];
    int base = blockIdx.x * NC;
    int t = threadIdx.x;
    int local[32];
    int sum = 0;
#pragma unroll
    for (int k = 0; k < 32; k++) {
        int c = g_cnt[base + t * 32 + k];
        local[k] = sum;
        sum += c;
    }
    sm[t] = sum;
    __syncthreads();
    for (int off = 1; off < 1024; off <<= 1) {
        int v = (t >= off) ? sm[t - off] : 0;
        __syncthreads();
        sm[t] += v;
        __syncthreads();
    }
    int excl = (t == 0) ? 0 : sm[t - 1];
    int gbase = blockIdx.x * NN;
#pragma unroll
    for (int k = 0; k < 32; k++) {
        int s = gbase + excl + local[k];
        g_cstart[base + t * 32 + k] = s;
        g_ccur[base + t * 32 + k] = s;
    }
    if (blockIdx.x == 0 && t == 0) g_cstart[BB * NC] = BB * NN;
}

__global__ void scatter_kernel(const float* __restrict__ xyz)
{
    int i = blockIdx.x * blockDim.x + threadIdx.x;
    if (i >= BB * NN) return;
    int b = i >> 14;
    int cell = g_cell[i];
    int pos = atomicAdd(&g_ccur[b * NC + cell], 1);
    const float* p = xyz + (size_t)i * 3;
    float x = p[0], y = p[1], z = p[2];
    float pp = __fadd_rn(__fadd_rn(__fmul_rn(x, x), __fmul_rn(y, y)),
                         __fmul_rn(z, z));
    g_pts[pos] = make_float4(x, y, z, pp);
    g_pidx[pos] = i & (NN - 1);
}

// ---------------- binned KNN: warp per query, expanding rings ----------------
// Distances bitwise-identical to R5/R7:
//   qq, pp : (x*x + y*y) + z*z, mul+add, NO fma
//   dot2   : fma(2qz,pz, fma(2qy,py, rn(2qx*px))) == 2*dot bitwise
//   d      : (qq - dot2) + pp, NO fma
// Top-32 kept as warp-distributed sorted list of (d, idx) lexicographic —
// result is order-independent, so cell-sorted scanning is exact.
__device__ __forceinline__ void scan_cell(
    int cid, int lane, float qx2, float qy2, float qz2, float qq,
    float& kd, float& ld, int& li)
{
    const unsigned FULL = 0xffffffffu;
    int s = g_cstart[cid];
    int e = g_cstart[cid + 1];
    for (int j = s; j < e; j += 32) {
        int jj = j + lane;
        bool v = jj < e;
        float d = __int_as_float(0x7f800000);
        int ci = 0x7fffffff;
        if (v) {
            float4 p = g_pts[jj];
            ci = g_pidx[jj];
            float dot2 = __fmaf_rn(qz2, p.z,
                         __fmaf_rn(qy2, p.y, __fmul_rn(qx2, p.x)));
            d = __fadd_rn(__fsub_rn(qq, dot2), p.w);
        }
        unsigned m = __ballot_sync(FULL, v && d <= kd);
        if (m) {
            do {
                int src = __ffs(m) - 1;
                m &= m - 1;
                float cd = __shfl_sync(FULL, d, src);
                int   cc = __shfl_sync(FULL, ci, src);
                bool eb = (ld < cd) || (ld == cd && li < cc);
                int pos = __popc(__ballot_sync(FULL, eb));
                float sd = __shfl_up_sync(FULL, ld, 1);
                int   si = __shfl_up_sync(FULL, li, 1);
                if (lane == pos)      { ld = cd; li = cc; }
                else if (lane > pos)  { ld = sd; li = si; }
            } while (m);
            kd = __shfl_sync(FULL, ld, 31);
        }
    }
}

__global__ void __launch_bounds__(256)
knn_kernel(const float* __restrict__ xyz, const int* __restrict__ sidx,
           float* __restrict__ out)
{
    const unsigned FULL = 0xffffffffu;
    int warp = threadIdx.x >> 5;
    int lane = threadIdx.x & 31;
    int qid = blockIdx.x * 8 + warp;               // global sample row
    int b = qid >> 12;

    int sid = sidx[qid];
    const float* qp = xyz + ((size_t)b * NN + sid) * 3;
    float x = qp[0], y = qp[1], z = qp[2];
    float qq = __fadd_rn(__fadd_rn(__fmul_rn(x, x), __fmul_rn(y, y)),
                         __fmul_rn(z, z));
    float qx2 = 2.0f * x, qy2 = 2.0f * y, qz2 = 2.0f * z;

    if (lane == 0) {                                // fold meta outputs
        out[qid * 3 + 0] = x;
        out[qid * 3 + 1] = y;
        out[qid * 3 + 2] = z;
        out[(size_t)BB * SS * 3 + (size_t)BB * SS * C3 + qid] = (float)sid;
    }

    int cx = min(GG - 1, max(0, (int)floorf((x + BOUNDF) * (1.0f / HH))));
    int cy = min(GG - 1, max(0, (int)floorf((y + BOUNDF) * (1.0f / HH))));
    int cz = min(GG - 1, max(0, (int)floorf((z + BOUNDF) * (1.0f / HH))));
    int cbase = b * NC;

    float ld = __int_as_float(0x7f800000);
    int   li = 0x7fffffff;
    float kd = ld;

    for (int r = 0; r < GG; r++) {
        int zlo = max(cz - r, 0), zhi = min(cz + r, GG - 1);
        for (int zc = zlo; zc <= zhi; zc++) {
            int adz = (zc > cz) ? (zc - cz) : (cz - zc);
            int ylo = max(cy - r, 0), yhi = min(cy + r, GG - 1);
            for (int yc = ylo; yc <= yhi; yc++) {
                int ady = (yc > cy) ? (yc - cy) : (cy - yc);
                if (adz == r || ady == r) {
                    int xlo = max(cx - r, 0), xhi = min(cx + r, GG - 1);
                    for (int xc = xlo; xc <= xhi; xc++)
                        scan_cell(cbase + (xc * GG + yc) * GG + zc,
                                  lane, qx2, qy2, qz2, qq, kd, ld, li);
                } else {
                    int x1 = cx - r;
                    if (x1 >= 0)
                        scan_cell(cbase + (x1 * GG + yc) * GG + zc,
                                  lane, qx2, qy2, qz2, qq, kd, ld, li);
                    int x2 = cx + r;
                    if (x2 < GG)
                        scan_cell(cbase + (x2 * GG + yc) * GG + zc,
                                  lane, qx2, qy2, qz2, qq, kd, ld, li);
                }
            }
        }
        // rings >= r+1 hold points at true dist >= r*HH (clamped points are
        // strictly farther than their boundary cell implies -> still safe)
        float rb = (float)r * HH;
        if (kd < rb * rb - MARGIN) break;
    }

    g_knn[(size_t)qid * KK + lane] = li;
}

// ---------------- distributed warp max-reduce stage ----------------
template <int M, int SH>
__device__ __forceinline__ void redstage(float* o, int l)
{
    int bit = (l >> SH) & 1;
#pragma unroll
    for (int i = 0; i < M; i++) {
        float snd = bit ? o[i] : o[M + i];
        float rcv = __shfl_xor_sync(0xffffffffu, snd, 1 << SH);
        float mine = bit ? o[M + i] : o[i];
        o[i] = fmaxf(mine, rcv);
    }
}

// ---------------- MLP + maxpool: warp per query, lane per neighbor ----------------
__global__ void __launch_bounds__(256)
mlp_kernel(const float* __restrict__ xyz, const float* __restrict__ feat,
           const int* __restrict__ sidx,
           const float* __restrict__ w1g, const float* __restrict__ w2g,
           const float* __restrict__ w3g,
           float* __restrict__ out)
{
    __shared__ float sW1[C0 * C1], sW2[C1 * C2], sW3[C2 * C3];
    __shared__ float sA1[C1], sB1[C1], sA2[C2], sB2[C2], sA3[C3], sB3[C3];
    for (int i = threadIdx.x; i < C0 * C1; i += 256) sW1[i] = w1g[i];
    for (int i = threadIdx.x; i < C1 * C2; i += 256) sW2[i] = w2g[i];
    for (int i = threadIdx.x; i < C2 * C3; i += 256) sW3[i] = w3g[i];
    if (threadIdx.x < C1) { sA1[threadIdx.x] = g_a1[threadIdx.x]; sB1[threadIdx.x] = g_b1[threadIdx.x]; }
    if (threadIdx.x < C2) { sA2[threadIdx.x] = g_a2[threadIdx.x]; sB2[threadIdx.x] = g_b2[threadIdx.x]; }
    if (threadIdx.x < C3) { sA3[threadIdx.x] = g_a3[threadIdx.x]; sB3[threadIdx.x] = g_b3[threadIdx.x]; }
    __syncthreads();

    int warp = threadIdx.x >> 5;
    int lane = threadIdx.x & 31;
    int qid = blockIdx.x * 8 + warp;
    int b = qid >> 12;

    int sid = sidx[qid];
    const float* qp = xyz + ((size_t)b * NN + sid) * 3;
    float qx = qp[0], qy = qp[1], qz = qp[2];

    int nb = g_knn[(size_t)qid * KK + lane];
    const float* pp = xyz + ((size_t)b * NN + nb) * 3;

    float x[C0];
    x[0] = pp[0] - qx;
    x[1] = pp[1] - qy;
    x[2] = pp[2] - qz;
    const float4* f4 = (const float4*)(feat + ((size_t)b * NN + nb) * CINF);
#pragma unroll
    for (int v = 0; v < 4; v++) {
        float4 fv = f4[v];
        x[3 + 4 * v] = fv.x; x[4 + 4 * v] = fv.y;
        x[5 + 4 * v] = fv.z; x[6 + 4 * v] = fv.w;
    }

    float y[C1];
#pragma unroll
    for (int d = 0; d < C1; d++) y[d] = 0.0f;
    {
        const float4* Wv = (const float4*)sW1;
#pragma unroll
        for (int c = 0; c < C0; c++) {
            float xc = x[c];
#pragma unroll
            for (int d4 = 0; d4 < C1 / 4; d4++) {
                float4 wv = Wv[c * (C1 / 4) + d4];
                y[4 * d4 + 0] = fmaf(xc, wv.x, y[4 * d4 + 0]);
                y[4 * d4 + 1] = fmaf(xc, wv.y, y[4 * d4 + 1]);
                y[4 * d4 + 2] = fmaf(xc, wv.z, y[4 * d4 + 2]);
                y[4 * d4 + 3] = fmaf(xc, wv.w, y[4 * d4 + 3]);
            }
        }
    }
#pragma unroll
    for (int d = 0; d < C1; d++)
        y[d] = fmaxf(fmaf(y[d], sA1[d], sB1[d]), 0.0f);

    float z[C2];
#pragma unroll
    for (int d = 0; d < C2; d++) z[d] = 0.0f;
    {
        const float4* Wv = (const float4*)sW2;
#pragma unroll
        for (int c = 0; c < C1; c++) {
            float xc = y[c];
#pragma unroll
            for (int d4 = 0; d4 < C2 / 4; d4++) {
                float4 wv = Wv[c * (C2 / 4) + d4];
                z[4 * d4 + 0] = fmaf(xc, wv.x, z[4 * d4 + 0]);
                z[4 * d4 + 1] = fmaf(xc, wv.y, z[4 * d4 + 1]);
                z[4 * d4 + 2] = fmaf(xc, wv.z, z[4 * d4 + 2]);
                z[4 * d4 + 3] = fmaf(xc, wv.w, z[4 * d4 + 3]);
            }
        }
    }
#pragma unroll
    for (int d = 0; d < C2; d++)
        z[d] = fmaxf(fmaf(z[d], sA2[d], sB2[d]), 0.0f);

    float o[C3];
#pragma unroll
    for (int d = 0; d < C3; d++) o[d] = 0.0f;
    {
        const float4* Wv = (const float4*)sW3;
#pragma unroll
        for (int c = 0; c < C2; c++) {
            float xc = z[c];
#pragma unroll
            for (int d4 = 0; d4 < C3 / 4; d4++) {
                float4 wv = Wv[c * (C3 / 4) + d4];
                o[4 * d4 + 0] = fmaf(xc, wv.x, o[4 * d4 + 0]);
                o[4 * d4 + 1] = fmaf(xc, wv.y, o[4 * d4 + 1]);
                o[4 * d4 + 2] = fmaf(xc, wv.z, o[4 * d4 + 2]);
                o[4 * d4 + 3] = fmaf(xc, wv.w, o[4 * d4 + 3]);
            }
        }
    }
#pragma unroll
    for (int d = 0; d < C3; d++)
        o[d] = fmaxf(fmaf(o[d], sA3[d], sB3[d]), 0.0f);

    redstage<32, 0>(o, lane);
    redstage<16, 1>(o, lane);
    redstage<8,  2>(o, lane);
    redstage<4,  3>(o, lane);
    redstage<2,  4>(o, lane);

    int chb = (((lane >> 0) & 1) << 5) | (((lane >> 1) & 1) << 4) |
              (((lane >> 2) & 1) << 3) | (((lane >> 3) & 1) << 2) |
              (((lane >> 4) & 1) << 1);

    float* dst = out + (size_t)BB * SS * 3 + (size_t)qid * C3 + chb;
    *(float2*)dst = make_float2(o[0], o[1]);
}

// ---------------- launch ----------------
extern "C" void kernel_launch(void* const* d_in, const int* in_sizes, int n_in,
                              void* d_out, int out_size)
{
    const float* xyz     = (const float*)d_in[0];
    const float* feature = (const float*)d_in[1];
    const int*   sidx    = (const int*)d_in[2];

    const float* w0  = (const float*)d_in[3];
    const float* b0  = (const float*)d_in[4];
    const float* g0  = (const float*)d_in[5];
    const float* bt0 = (const float*)d_in[6];
    const float* rm0 = (const float*)d_in[7];
    const float* rv0 = (const float*)d_in[8];
    const float* w1  = (const float*)d_in[9];
    const float* b1  = (const float*)d_in[10];
    const float* g1  = (const float*)d_in[11];
    const float* bt1 = (const float*)d_in[12];
    const float* rm1 = (const float*)d_in[13];
    const float* rv1 = (const float*)d_in[14];
    const float* w2  = (const float*)d_in[15];
    const float* b2  = (const float*)d_in[16];
    const float* g2  = (const float*)d_in[17];
    const float* bt2 = (const float*)d_in[18];
    const float* rm2 = (const float*)d_in[19];
    const float* rv2 = (const float*)d_in[20];

    float* out = (float*)d_out;

    prep_kernel<<<1, 256>>>(b0, g0, bt0, rm0, rv0,
                            b1, g1, bt1, rm1, rv1,
                            b2, g2, bt2, rm2, rv2);
    zero_kernel<<<(BB * NC + 255) / 256, 256>>>();
    count_kernel<<<(BB * NN + 255) / 256, 256>>>(xyz);
    scan_kernel<<<BB, 1024>>>();
    scatter_kernel<<<(BB * NN + 255) / 256, 256>>>(xyz);
    knn_kernel<<<(BB * SS) / 8, 256>>>(xyz, sidx, out);
    mlp_kernel<<<(BB * SS) / 8, 256>>>(xyz, feature, sidx, w0, w1, w2, out);
}

// round 9
// speedup vs baseline: 1.7374x; 1.7374x over previous
#include <cuda_runtime.h>
#include <cstdint>

#define BB  4
#define NN  16384
#define SS  4096
#define KK  32
#define CINF 16
#define C0  19
#define C1  32
#define C2  32
#define C3  64
#define EPSF 1e-5f

// spatial grid
#define GG     32
#define NC     (GG * GG * GG)
#define BOUNDF 4.5f
#define HH     (9.0f / (float)GG)
#define MARGIN 1e-3f

// ---------------- scratch (no allocs allowed) ----------------
__device__ int    g_knn[BB * SS * KK];
__device__ float  g_a1[C1], g_b1[C1];
__device__ float  g_a2[C2], g_b2[C2];
__device__ float  g_a3[C3], g_b3[C3];

__device__ float4 g_pts[BB * NN];        // cell-sorted (x, y, z, ||p||^2)
__device__ int    g_pidx[BB * NN];       // in-batch original index
__device__ int    g_cell[BB * NN];       // cell id per original point
__device__ int    g_cnt[BB * NC];
__device__ int    g_cstart[BB * NC + 1];
__device__ int    g_ccur[BB * NC];

// ---------------- prep: fold BN as post-affine ----------------
__global__ void prep_kernel(
    const float* __restrict__ b0,
    const float* __restrict__ g0, const float* __restrict__ bt0,
    const float* __restrict__ rm0, const float* __restrict__ rv0,
    const float* __restrict__ b1,
    const float* __restrict__ g1, const float* __restrict__ bt1,
    const float* __restrict__ rm1, const float* __restrict__ rv1,
    const float* __restrict__ b2,
    const float* __restrict__ g2, const float* __restrict__ bt2,
    const float* __restrict__ rm2, const float* __restrict__ rv2)
{
    int t = threadIdx.x;
    if (t < C1) {
        float A = g0[t] * rsqrtf(rv0[t] + EPSF);
        g_a1[t] = A;
        g_b1[t] = (b0[t] - rm0[t]) * A + bt0[t];
    }
    if (t < C2) {
        float A = g1[t] * rsqrtf(rv1[t] + EPSF);
        g_a2[t] = A;
        g_b2[t] = (b1[t] - rm1[t]) * A + bt1[t];
    }
    if (t < C3) {
        float A = g2[t] * rsqrtf(rv2[t] + EPSF);
        g_a3[t] = A;
        g_b3[t] = (b2[t] - rm2[t]) * A + bt2[t];
    }
}

// ---------------- binning ----------------
__global__ void zero_kernel()
{
    int i = blockIdx.x * blockDim.x + threadIdx.x;
    if (i < BB * NC) g_cnt[i] = 0;
}

__device__ __forceinline__ int clampi(int v) { return min(GG - 1, max(0, v)); }

__device__ __forceinline__ int cell_of(float x, float y, float z)
{
    int cx = clampi((int)floorf((x + BOUNDF) * (1.0f / HH)));
    int cy = clampi((int)floorf((y + BOUNDF) * (1.0f / HH)));
    int cz = clampi((int)floorf((z + BOUNDF) * (1.0f / HH)));
    return (cx * GG + cy) * GG + cz;
}

__global__ void count_kernel(const float* __restrict__ xyz)
{
    int i = blockIdx.x * blockDim.x + threadIdx.x;
    if (i >= BB * NN) return;
    int b = i >> 14;
    const float* p = xyz + (size_t)i * 3;
    int cell = cell_of(p[0], p[1], p[2]);
    g_cell[i] = cell;
    atomicAdd(&g_cnt[b * NC + cell], 1);
}

__global__ void scan_kernel()   // grid = BB, block = 1024; 32 cells/thread
{
    __shared__ int wsum[32];
    const unsigned FULL = 0xffffffffu;
    int t = threadIdx.x, lane = t & 31, w = t >> 5;
    int base = blockIdx.x * NC;
    int local[32];
    int sum = 0;
#pragma unroll
    for (int k = 0; k < 32; k++) {
        local[k] = sum;
        sum += g_cnt[base + t * 32 + k];
    }
    int v = sum;                                   // inclusive warp scan
#pragma unroll
    for (int o = 1; o < 32; o <<= 1) {
        int u = __shfl_up_sync(FULL, v, o);
        if (lane >= o) v += u;
    }
    if (lane == 31) wsum[w] = v;
    __syncthreads();
    if (w == 0) {
        int s = wsum[lane];
#pragma unroll
        for (int o = 1; o < 32; o <<= 1) {
            int u = __shfl_up_sync(FULL, s, o);
            if (lane >= o) s += u;
        }
        wsum[lane] = s;
    }
    __syncthreads();
    int excl = v - sum + ((w > 0) ? wsum[w - 1] : 0);
    int gbase = blockIdx.x * NN;
#pragma unroll
    for (int k = 0; k < 32; k++) {
        int s = gbase + excl + local[k];
        g_cstart[base + t * 32 + k] = s;
        g_ccur[base + t * 32 + k] = s;
    }
    if (blockIdx.x == 0 && t == 0) g_cstart[BB * NC] = BB * NN;
}

__global__ void scatter_kernel(const float* __restrict__ xyz)
{
    int i = blockIdx.x * blockDim.x + threadIdx.x;
    if (i >= BB * NN) return;
    int b = i >> 14;
    int cell = g_cell[i];
    int pos = atomicAdd(&g_ccur[b * NC + cell], 1);
    const float* p = xyz + (size_t)i * 3;
    float x = p[0], y = p[1], z = p[2];
    float pp = __fadd_rn(__fadd_rn(__fmul_rn(x, x), __fmul_rn(y, y)),
                         __fmul_rn(z, z));
    g_pts[pos] = make_float4(x, y, z, pp);
    g_pidx[pos] = i & (NN - 1);
}

// ---------------- binned KNN v2: column-segment scans ----------------
// Distances bitwise-identical to R5/R7/R8 (validated):
//   qq, pp : (x*x + y*y) + z*z, mul+add, NO fma
//   dot2   : fma(2qz,pz, fma(2qy,py, rn(2qx*px))) == 2*dot bitwise
//   d      : (qq - dot2) + pp, NO fma
// Warp-distributed sorted top-32 of (d, idx); order-independent.
__device__ __forceinline__ void scan_range(
    int s, int e, int lane, float qx2, float qy2, float qz2, float qq,
    float& kd, float& ld, int& li)
{
    const unsigned FULL = 0xffffffffu;
    for (int j = s; j < e; j += 32) {
        int jj = j + lane;
        bool v = jj < e;
        float d = __int_as_float(0x7f800000);
        int ci = 0x7fffffff;
        if (v) {
            float4 p = g_pts[jj];
            ci = g_pidx[jj];
            float dot2 = __fmaf_rn(qz2, p.z,
                         __fmaf_rn(qy2, p.y, __fmul_rn(qx2, p.x)));
            d = __fadd_rn(__fsub_rn(qq, dot2), p.w);
        }
        unsigned m = __ballot_sync(FULL, v && d <= kd);
        if (m) {
            do {
                int src = __ffs(m) - 1;
                m &= m - 1;
                float cd = __shfl_sync(FULL, d, src);
                int   cc = __shfl_sync(FULL, ci, src);
                bool eb = (ld < cd) || (ld == cd && li < cc);
                int pos = __popc(__ballot_sync(FULL, eb));
                float sd = __shfl_up_sync(FULL, ld, 1);
                int   si = __shfl_up_sync(FULL, li, 1);
                if (lane == pos)      { ld = cd; li = cc; }
                else if (lane > pos)  { ld = sd; li = si; }
            } while (m);
            kd = __shfl_sync(FULL, ld, 31);
        }
    }
}

__global__ void __launch_bounds__(256)
knn_kernel(const float* __restrict__ xyz, const int* __restrict__ sidx,
           float* __restrict__ out)
{
    const unsigned FULL = 0xffffffffu;
    int warp = threadIdx.x >> 5;
    int lane = threadIdx.x & 31;
    int qid = blockIdx.x * 8 + warp;
    int b = qid >> 12;

    int sid = sidx[qid];
    const float* qp = xyz + ((size_t)b * NN + sid) * 3;
    float x = qp[0], y = qp[1], z = qp[2];
    float qq = __fadd_rn(__fadd_rn(__fmul_rn(x, x), __fmul_rn(y, y)),
                         __fmul_rn(z, z));
    float qx2 = 2.0f * x, qy2 = 2.0f * y, qz2 = 2.0f * z;

    if (lane == 0) {                                // fold meta outputs
        out[qid * 3 + 0] = x;
        out[qid * 3 + 1] = y;
        out[qid * 3 + 2] = z;
        out[(size_t)BB * SS * 3 + (size_t)BB * SS * C3 + qid] = (float)sid;
    }

    int cx = clampi((int)floorf((x + BOUNDF) * (1.0f / HH)));
    int cy = clampi((int)floorf((y + BOUNDF) * (1.0f / HH)));
    int cz = clampi((int)floorf((z + BOUNDF) * (1.0f / HH)));
    int cbase = b * NC;

    // ---- Phase A: pick starting radius (box count >= 48 or box = grid) ----
    int r = 1;
    for (;; r++) {
        bool full = (cx - r <= 0) && (cx + r >= GG - 1) &&
                    (cy - r <= 0) && (cy + r >= GG - 1) &&
                    (cz - r <= 0) && (cz + r >= GG - 1);
        int n = 2 * r + 1, nxy = n * n;
        int zlo = max(cz - r, 0), zhi = min(cz + r, GG - 1);
        int total = 0;
        for (int basec = 0; basec < nxy; basec += 32) {
            int idx = basec + lane;
            int cnt = 0;
            if (idx < nxy) {
                int xx = cx + idx / n - r, yy = cy + idx % n - r;
                if (xx >= 0 && xx < GG && yy >= 0 && yy < GG) {
                    int cid = cbase + (xx * GG + yy) * GG;
                    cnt = g_cstart[cid + zhi + 1] - g_cstart[cid + zlo];
                }
            }
#pragma unroll
            for (int o = 16; o; o >>= 1) cnt += __shfl_xor_sync(FULL, cnt, o);
            total += cnt;
        }
        if (total >= 48 || full) break;
    }

    float ld = __int_as_float(0x7f800000);
    int   li = 0x7fffffff;
    float kd = ld;

    // ---- Phase B: scan box radius r as column segments ----
    {
        int n = 2 * r + 1, nxy = n * n;
        int zlo = max(cz - r, 0), zhi = min(cz + r, GG - 1);
        for (int basec = 0; basec < nxy; basec += 32) {
            int idx = basec + lane;
            int s0 = 0, e0 = 0;
            if (idx < nxy) {
                int xx = cx + idx / n - r, yy = cy + idx % n - r;
                if (xx >= 0 && xx < GG && yy >= 0 && yy < GG) {
                    int cid = cbase + (xx * GG + yy) * GG;
                    s0 = g_cstart[cid + zlo];
                    e0 = g_cstart[cid + zhi + 1];
                }
            }
            int lim = min(32, nxy - basec);
            for (int c = 0; c < lim; c++) {
                int s = __shfl_sync(FULL, s0, c);
                int e = __shfl_sync(FULL, e0, c);
                if (s < e) scan_range(s, e, lane, qx2, qy2, qz2, qq, kd, ld, li);
            }
        }
    }

    // ---- expand shells until safety bound holds (validated in R8) ----
    for (;;) {
        bool full = (cx - r <= 0) && (cx + r >= GG - 1) &&
                    (cy - r <= 0) && (cy + r >= GG - 1) &&
                    (cz - r <= 0) && (cz + r >= GG - 1);
        float rb = (float)r * HH;
        if (full || kd < rb * rb - MARGIN) break;
        r++;
        int n = 2 * r + 1, nxy = n * n;
        int zlo = max(cz - r, 0), zhi = min(cz + r, GG - 1);
        for (int basec = 0; basec < nxy; basec += 32) {
            int idx = basec + lane;
            int s1 = 0, e1 = 0, s2 = 0, e2 = 0;
            if (idx < nxy) {
                int dx = idx / n - r, dy = idx % n - r;
                int xx = cx + dx, yy = cy + dy;
                if (xx >= 0 && xx < GG && yy >= 0 && yy < GG) {
                    int cid = cbase + (xx * GG + yy) * GG;
                    int adx = (dx < 0) ? -dx : dx, ady = (dy < 0) ? -dy : dy;
                    if (adx == r || ady == r) {          // new perimeter column
                        s1 = g_cstart[cid + zlo];
                        e1 = g_cstart[cid + zhi + 1];
                    } else {                              // two new z cells
                        int z1 = cz - r;
                        if (z1 >= 0) { s1 = g_cstart[cid + z1]; e1 = g_cstart[cid + z1 + 1]; }
                        int z2 = cz + r;
                        if (z2 < GG) { s2 = g_cstart[cid + z2]; e2 = g_cstart[cid + z2 + 1]; }
                    }
                }
            }
            int lim = min(32, nxy - basec);
            for (int c = 0; c < lim; c++) {
                int s = __shfl_sync(FULL, s1, c);
                int e = __shfl_sync(FULL, e1, c);
                if (s < e) scan_range(s, e, lane, qx2, qy2, qz2, qq, kd, ld, li);
                s = __shfl_sync(FULL, s2, c);
                e = __shfl_sync(FULL, e2, c);
                if (s < e) scan_range(s, e, lane, qx2, qy2, qz2, qq, kd, ld, li);
            }
        }
    }

    g_knn[(size_t)qid * KK + lane] = li;
}

// ---------------- distributed warp max-reduce stage ----------------
template <int M, int SH>
__device__ __forceinline__ void redstage(float* o, int l)
{
    int bit = (l >> SH) & 1;
#pragma unroll
    for (int i = 0; i < M; i++) {
        float snd = bit ? o[i] : o[M + i];
        float rcv = __shfl_xor_sync(0xffffffffu, snd, 1 << SH);
        float mine = bit ? o[M + i] : o[i];
        o[i] = fmaxf(mine, rcv);
    }
}

// ---------------- MLP + maxpool: warp per query, lane per neighbor ----------------
__global__ void __launch_bounds__(256)
mlp_kernel(const float* __restrict__ xyz, const float* __restrict__ feat,
           const int* __restrict__ sidx,
           const float* __restrict__ w1g, const float* __restrict__ w2g,
           const float* __restrict__ w3g,
           float* __restrict__ out)
{
    __shared__ float sW1[C0 * C1], sW2[C1 * C2], sW3[C2 * C3];
    __shared__ float sA1[C1], sB1[C1], sA2[C2], sB2[C2], sA3[C3], sB3[C3];
    for (int i = threadIdx.x; i < C0 * C1; i += 256) sW1[i] = w1g[i];
    for (int i = threadIdx.x; i < C1 * C2; i += 256) sW2[i] = w2g[i];
    for (int i = threadIdx.x; i < C2 * C3; i += 256) sW3[i] = w3g[i];
    if (threadIdx.x < C1) { sA1[threadIdx.x] = g_a1[threadIdx.x]; sB1[threadIdx.x] = g_b1[threadIdx.x]; }
    if (threadIdx.x < C2) { sA2[threadIdx.x] = g_a2[threadIdx.x]; sB2[threadIdx.x] = g_b2[threadIdx.x]; }
    if (threadIdx.x < C3) { sA3[threadIdx.x] = g_a3[threadIdx.x]; sB3[threadIdx.x] = g_b3[threadIdx.x]; }
    __syncthreads();

    int warp = threadIdx.x >> 5;
    int lane = threadIdx.x & 31;
    int qid = blockIdx.x * 8 + warp;
    int b = qid >> 12;

    int sid = sidx[qid];
    const float* qp = xyz + ((size_t)b * NN + sid) * 3;
    float qx = qp[0], qy = qp[1], qz = qp[2];

    int nb = g_knn[(size_t)qid * KK + lane];
    const float* pp = xyz + ((size_t)b * NN + nb) * 3;

    float x[C0];
    x[0] = pp[0] - qx;
    x[1] = pp[1] - qy;
    x[2] = pp[2] - qz;
    const float4* f4 = (const float4*)(feat + ((size_t)b * NN + nb) * CINF);
#pragma unroll
    for (int v = 0; v < 4; v++) {
        float4 fv = f4[v];
        x[3 + 4 * v] = fv.x; x[4 + 4 * v] = fv.y;
        x[5 + 4 * v] = fv.z; x[6 + 4 * v] = fv.w;
    }

    float y[C1];
#pragma unroll
    for (int d = 0; d < C1; d++) y[d] = 0.0f;
    {
        const float4* Wv = (const float4*)sW1;
#pragma unroll
        for (int c = 0; c < C0; c++) {
            float xc = x[c];
#pragma unroll
            for (int d4 = 0; d4 < C1 / 4; d4++) {
                float4 wv = Wv[c * (C1 / 4) + d4];
                y[4 * d4 + 0] = fmaf(xc, wv.x, y[4 * d4 + 0]);
                y[4 * d4 + 1] = fmaf(xc, wv.y, y[4 * d4 + 1]);
                y[4 * d4 + 2] = fmaf(xc, wv.z, y[4 * d4 + 2]);
                y[4 * d4 + 3] = fmaf(xc, wv.w, y[4 * d4 + 3]);
            }
        }
    }
#pragma unroll
    for (int d = 0; d < C1; d++)
        y[d] = fmaxf(fmaf(y[d], sA1[d], sB1[d]), 0.0f);

    float z[C2];
#pragma unroll
    for (int d = 0; d < C2; d++) z[d] = 0.0f;
    {
        const float4* Wv = (const float4*)sW2;
#pragma unroll
        for (int c = 0; c < C1; c++) {
            float xc = y[c];
#pragma unroll
            for (int d4 = 0; d4 < C2 / 4; d4++) {
                float4 wv = Wv[c * (C2 / 4) + d4];
                z[4 * d4 + 0] = fmaf(xc, wv.x, z[4 * d4 + 0]);
                z[4 * d4 + 1] = fmaf(xc, wv.y, z[4 * d4 + 1]);
                z[4 * d4 + 2] = fmaf(xc, wv.z, z[4 * d4 + 2]);
                z[4 * d4 + 3] = fmaf(xc, wv.w, z[4 * d4 + 3]);
            }
        }
    }
#pragma unroll
    for (int d = 0; d < C2; d++)
        z[d] = fmaxf(fmaf(z[d], sA2[d], sB2[d]), 0.0f);

    float o[C3];
#pragma unroll
    for (int d = 0; d < C3; d++) o[d] = 0.0f;
    {
        const float4* Wv = (const float4*)sW3;
#pragma unroll
        for (int c = 0; c < C2; c++) {
            float xc = z[c];
#pragma unroll
            for (int d4 = 0; d4 < C3 / 4; d4++) {
                float4 wv = Wv[c * (C3 / 4) + d4];
                o[4 * d4 + 0] = fmaf(xc, wv.x, o[4 * d4 + 0]);
                o[4 * d4 + 1] = fmaf(xc, wv.y, o[4 * d4 + 1]);
                o[4 * d4 + 2] = fmaf(xc, wv.z, o[4 * d4 + 2]);
                o[4 * d4 + 3] = fmaf(xc, wv.w, o[4 * d4 + 3]);
            }
        }
    }
#pragma unroll
    for (int d = 0; d < C3; d++)
        o[d] = fmaxf(fmaf(o[d], sA3[d], sB3[d]), 0.0f);

    redstage<32, 0>(o, lane);
    redstage<16, 1>(o, lane);
    redstage<8,  2>(o, lane);
    redstage<4,  3>(o, lane);
    redstage<2,  4>(o, lane);

    int chb = (((lane >> 0) & 1) << 5) | (((lane >> 1) & 1) << 4) |
              (((lane >> 2) & 1) << 3) | (((lane >> 3) & 1) << 2) |
              (((lane >> 4) & 1) << 1);

    float* dst = out + (size_t)BB * SS * 3 + (size_t)qid * C3 + chb;
    *(float2*)dst = make_float2(o[0], o[1]);
}

// ---------------- launch ----------------
extern "C" void kernel_launch(void* const* d_in, const int* in_sizes, int n_in,
                              void* d_out, int out_size)
{
    const float* xyz     = (const float*)d_in[0];
    const float* feature = (const float*)d_in[1];
    const int*   sidx    = (const int*)d_in[2];

    const float* w0  = (const float*)d_in[3];
    const float* b0  = (const float*)d_in[4];
    const float* g0  = (const float*)d_in[5];
    const float* bt0 = (const float*)d_in[6];
    const float* rm0 = (const float*)d_in[7];
    const float* rv0 = (const float*)d_in[8];
    const float* w1  = (const float*)d_in[9];
    const float* b1  = (const float*)d_in[10];
    const float* g1  = (const float*)d_in[11];
    const float* bt1 = (const float*)d_in[12];
    const float* rm1 = (const float*)d_in[13];
    const float* rv1 = (const float*)d_in[14];
    const float* w2  = (const float*)d_in[15];
    const float* b2  = (const float*)d_in[16];
    const float* g2  = (const float*)d_in[17];
    const float* bt2 = (const float*)d_in[18];
    const float* rm2 = (const float*)d_in[19];
    const float* rv2 = (const float*)d_in[20];

    float* out = (float*)d_out;

    prep_kernel<<<1, 256>>>(b0, g0, bt0, rm0, rv0,
                            b1, g1, bt1, rm1, rv1,
                            b2, g2, bt2, rm2, rv2);
    zero_kernel<<<(BB * NC + 255) / 256, 256>>>();
    count_kernel<<<(BB * NN + 255) / 256, 256>>>(xyz);
    scan_kernel<<<BB, 1024>>>();
    scatter_kernel<<<(BB * NN + 255) / 256, 256>>>(xyz);
    knn_kernel<<<(BB * SS) / 8, 256>>>(xyz, sidx, out);
    mlp_kernel<<<(BB * SS) / 8, 256>>>(xyz, feature, sidx, w0, w1, w2, out);
}

// round 10
// speedup vs baseline: 1.9439x; 1.1188x over previous
#include <cuda_runtime.h>
#include <cstdint>

#define BB  4
#define NN  16384
#define SS  4096
#define KK  32
#define CINF 16
#define C0  19
#define C1  32
#define C2  32
#define C3  64
#define EPSF 1e-5f

// spatial grid
#define GG     32
#define NC     (GG * GG * GG)
#define BOUNDF 4.5f
#define HH     (9.0f / (float)GG)
#define MARGIN 1e-3f

// ---------------- scratch (no allocs allowed) ----------------
__device__ int    g_knn[BB * SS * KK];
__device__ float  g_a1[C1], g_b1[C1];
__device__ float  g_a2[C2], g_b2[C2];
__device__ float  g_a3[C3], g_b3[C3];

__device__ float4 g_pts[BB * NN];        // cell-sorted (x, y, z, ||p||^2)
__device__ int    g_pidx[BB * NN];       // in-batch original index
__device__ int    g_cell[BB * NN];       // cell id per original point
__device__ int    g_cnt[BB * NC];
__device__ int    g_cstart[BB * NC + 1];
__device__ int    g_ccur[BB * NC];
__device__ int    g_bsum[BB * 32];
__device__ int    g_boff[BB * 32];

// ---------------- packed f32x2 helpers (bitwise == two scalar fma.rn) --------
__device__ __forceinline__ unsigned long long packf2(float v)
{
    unsigned long long r;
    asm("mov.b64 %0, {%1, %1};" : "=l"(r) : "f"(v));
    return r;
}
__device__ __forceinline__ void fma2(unsigned long long& a,
                                     unsigned long long x, unsigned long long w)
{
    asm("fma.rn.f32x2 %0, %1, %2, %0;" : "+l"(a) : "l"(x), "l"(w));
}
__device__ __forceinline__ void unpack2(unsigned long long a, float& lo, float& hi)
{
    asm("mov.b64 {%0, %1}, %2;" : "=f"(lo), "=f"(hi) : "l"(a));
}

// ---------------- prep: fold BN as post-affine ----------------
__global__ void prep_kernel(
    const float* __restrict__ b0,
    const float* __restrict__ g0, const float* __restrict__ bt0,
    const float* __restrict__ rm0, const float* __restrict__ rv0,
    const float* __restrict__ b1,
    const float* __restrict__ g1, const float* __restrict__ bt1,
    const float* __restrict__ rm1, const float* __restrict__ rv1,
    const float* __restrict__ b2,
    const float* __restrict__ g2, const float* __restrict__ bt2,
    const float* __restrict__ rm2, const float* __restrict__ rv2)
{
    int t = threadIdx.x;
    if (t < C1) {
        float A = g0[t] * rsqrtf(rv0[t] + EPSF);
        g_a1[t] = A;
        g_b1[t] = (b0[t] - rm0[t]) * A + bt0[t];
    }
    if (t < C2) {
        float A = g1[t] * rsqrtf(rv1[t] + EPSF);
        g_a2[t] = A;
        g_b2[t] = (b1[t] - rm1[t]) * A + bt1[t];
    }
    if (t < C3) {
        float A = g2[t] * rsqrtf(rv2[t] + EPSF);
        g_a3[t] = A;
        g_b3[t] = (b2[t] - rm2[t]) * A + bt2[t];
    }
}

// ---------------- binning ----------------
__global__ void zero_kernel()
{
    int i = blockIdx.x * blockDim.x + threadIdx.x;
    if (i < BB * NC) g_cnt[i] = 0;
}

__device__ __forceinline__ int clampi(int v) { return min(GG - 1, max(0, v)); }

__device__ __forceinline__ int cell_of(float x, float y, float z)
{
    int cx = clampi((int)floorf((x + BOUNDF) * (1.0f / HH)));
    int cy = clampi((int)floorf((y + BOUNDF) * (1.0f / HH)));
    int cz = clampi((int)floorf((z + BOUNDF) * (1.0f / HH)));
    return (cx * GG + cy) * GG + cz;
}

__global__ void count_kernel(const float* __restrict__ xyz)
{
    int i = blockIdx.x * blockDim.x + threadIdx.x;
    if (i >= BB * NN) return;
    int b = i >> 14;
    const float* p = xyz + (size_t)i * 3;
    int cell = cell_of(p[0], p[1], p[2]);
    g_cell[i] = cell;
    atomicAdd(&g_cnt[b * NC + cell], 1);
}

// hierarchical scan: (B) per-block scans, (C) scan of block sums, (D) add
__global__ void scanB_kernel()   // grid = BB*32, block = 1024, 1 cell/thread
{
    __shared__ int wsum[32];
    const unsigned FULL = 0xffffffffu;
    int t = threadIdx.x, lane = t & 31, w = t >> 5;
    int b = blockIdx.x >> 5, blk = blockIdx.x & 31;
    int cell = blk * 1024 + t;
    int cnt = g_cnt[b * NC + cell];
    int v = cnt;
#pragma unroll
    for (int o = 1; o < 32; o <<= 1) {
        int u = __shfl_up_sync(FULL, v, o);
        if (lane >= o) v += u;
    }
    if (lane == 31) wsum[w] = v;
    __syncthreads();
    if (w == 0) {
        int s = wsum[lane];
#pragma unroll
        for (int o = 1; o < 32; o <<= 1) {
            int u = __shfl_up_sync(FULL, s, o);
            if (lane >= o) s += u;
        }
        wsum[lane] = s;
    }
    __syncthreads();
    int excl = v - cnt + ((w > 0) ? wsum[w - 1] : 0);
    g_cstart[b * NC + cell] = excl;                 // block-local for now
    if (t == 1023) g_bsum[blockIdx.x] = excl + cnt; // block total
}

__global__ void scanC_kernel()   // 1 block, 128 threads; warp w = batch w
{
    const unsigned FULL = 0xffffffffu;
    int lane = threadIdx.x & 31, w = threadIdx.x >> 5;
    int v = g_bsum[w * 32 + lane];
    int inc = v;
#pragma unroll
    for (int o = 1; o < 32; o <<= 1) {
        int u = __shfl_up_sync(FULL, inc, o);
        if (lane >= o) inc += u;
    }
    g_boff[w * 32 + lane] = inc - v + w * NN;
}

__global__ void scanD_kernel()   // grid = BB*32, block = 1024
{
    int b = blockIdx.x >> 5, blk = blockIdx.x & 31;
    int cell = blk * 1024 + threadIdx.x;
    int off = g_boff[blockIdx.x];
    int i = b * NC + cell;
    int v = g_cstart[i] + off;
    g_cstart[i] = v;
    g_ccur[i] = v;
    if (blockIdx.x == 0 && threadIdx.x == 0) g_cstart[BB * NC] = BB * NN;
}

__global__ void scatter_kernel(const float* __restrict__ xyz)
{
    int i = blockIdx.x * blockDim.x + threadIdx.x;
    if (i >= BB * NN) return;
    int b = i >> 14;
    int cell = g_cell[i];
    int pos = atomicAdd(&g_ccur[b * NC + cell], 1);
    const float* p = xyz + (size_t)i * 3;
    float x = p[0], y = p[1], z = p[2];
    float pp = __fadd_rn(__fadd_rn(__fmul_rn(x, x), __fmul_rn(y, y)),
                         __fmul_rn(z, z));
    g_pts[pos] = make_float4(x, y, z, pp);
    g_pidx[pos] = i & (NN - 1);
}

// ---------------- binned KNN: column-segment scans (unchanged from R9) -------
__device__ __forceinline__ void scan_range(
    int s, int e, int lane, float qx2, float qy2, float qz2, float qq,
    float& kd, float& ld, int& li)
{
    const unsigned FULL = 0xffffffffu;
    for (int j = s; j < e; j += 32) {
        int jj = j + lane;
        bool v = jj < e;
        float d = __int_as_float(0x7f800000);
        int ci = 0x7fffffff;
        if (v) {
            float4 p = g_pts[jj];
            ci = g_pidx[jj];
            float dot2 = __fmaf_rn(qz2, p.z,
                         __fmaf_rn(qy2, p.y, __fmul_rn(qx2, p.x)));
            d = __fadd_rn(__fsub_rn(qq, dot2), p.w);
        }
        unsigned m = __ballot_sync(FULL, v && d <= kd);
        if (m) {
            do {
                int src = __ffs(m) - 1;
                m &= m - 1;
                float cd = __shfl_sync(FULL, d, src);
                int   cc = __shfl_sync(FULL, ci, src);
                bool eb = (ld < cd) || (ld == cd && li < cc);
                int pos = __popc(__ballot_sync(FULL, eb));
                float sd = __shfl_up_sync(FULL, ld, 1);
                int   si = __shfl_up_sync(FULL, li, 1);
                if (lane == pos)      { ld = cd; li = cc; }
                else if (lane > pos)  { ld = sd; li = si; }
            } while (m);
            kd = __shfl_sync(FULL, ld, 31);
        }
    }
}

__global__ void __launch_bounds__(256)
knn_kernel(const float* __restrict__ xyz, const int* __restrict__ sidx,
           float* __restrict__ out)
{
    const unsigned FULL = 0xffffffffu;
    int warp = threadIdx.x >> 5;
    int lane = threadIdx.x & 31;
    int qid = blockIdx.x * 8 + warp;
    int b = qid >> 12;

    int sid = sidx[qid];
    const float* qp = xyz + ((size_t)b * NN + sid) * 3;
    float x = qp[0], y = qp[1], z = qp[2];
    float qq = __fadd_rn(__fadd_rn(__fmul_rn(x, x), __fmul_rn(y, y)),
                         __fmul_rn(z, z));
    float qx2 = 2.0f * x, qy2 = 2.0f * y, qz2 = 2.0f * z;

    if (lane == 0) {                                // fold meta outputs
        out[qid * 3 + 0] = x;
        out[qid * 3 + 1] = y;
        out[qid * 3 + 2] = z;
        out[(size_t)BB * SS * 3 + (size_t)BB * SS * C3 + qid] = (float)sid;
    }

    int cx = clampi((int)floorf((x + BOUNDF) * (1.0f / HH)));
    int cy = clampi((int)floorf((y + BOUNDF) * (1.0f / HH)));
    int cz = clampi((int)floorf((z + BOUNDF) * (1.0f / HH)));
    int cbase = b * NC;

    // ---- Phase A: pick starting radius (box count >= 48 or box = grid) ----
    int r = 1;
    for (;; r++) {
        bool full = (cx - r <= 0) && (cx + r >= GG - 1) &&
                    (cy - r <= 0) && (cy + r >= GG - 1) &&
                    (cz - r <= 0) && (cz + r >= GG - 1);
        int n = 2 * r + 1, nxy = n * n;
        int zlo = max(cz - r, 0), zhi = min(cz + r, GG - 1);
        int total = 0;
        for (int basec = 0; basec < nxy; basec += 32) {
            int idx = basec + lane;
            int cnt = 0;
            if (idx < nxy) {
                int xx = cx + idx / n - r, yy = cy + idx % n - r;
                if (xx >= 0 && xx < GG && yy >= 0 && yy < GG) {
                    int cid = cbase + (xx * GG + yy) * GG;
                    cnt = g_cstart[cid + zhi + 1] - g_cstart[cid + zlo];
                }
            }
#pragma unroll
            for (int o = 16; o; o >>= 1) cnt += __shfl_xor_sync(FULL, cnt, o);
            total += cnt;
        }
        if (total >= 48 || full) break;
    }

    float ld = __int_as_float(0x7f800000);
    int   li = 0x7fffffff;
    float kd = ld;

    // ---- Phase B: scan box radius r as column segments ----
    {
        int n = 2 * r + 1, nxy = n * n;
        int zlo = max(cz - r, 0), zhi = min(cz + r, GG - 1);
        for (int basec = 0; basec < nxy; basec += 32) {
            int idx = basec + lane;
            int s0 = 0, e0 = 0;
            if (idx < nxy) {
                int xx = cx + idx / n - r, yy = cy + idx % n - r;
                if (xx >= 0 && xx < GG && yy >= 0 && yy < GG) {
                    int cid = cbase + (xx * GG + yy) * GG;
                    s0 = g_cstart[cid + zlo];
                    e0 = g_cstart[cid + zhi + 1];
                }
            }
            int lim = min(32, nxy - basec);
            for (int c = 0; c < lim; c++) {
                int s = __shfl_sync(FULL, s0, c);
                int e = __shfl_sync(FULL, e0, c);
                if (s < e) scan_range(s, e, lane, qx2, qy2, qz2, qq, kd, ld, li);
            }
        }
    }

    // ---- expand shells until safety bound holds ----
    for (;;) {
        bool full = (cx - r <= 0) && (cx + r >= GG - 1) &&
                    (cy - r <= 0) && (cy + r >= GG - 1) &&
                    (cz - r <= 0) && (cz + r >= GG - 1);
        float rb = (float)r * HH;
        if (full || kd < rb * rb - MARGIN) break;
        r++;
        int n = 2 * r + 1, nxy = n * n;
        int zlo = max(cz - r, 0), zhi = min(cz + r, GG - 1);
        for (int basec = 0; basec < nxy; basec += 32) {
            int idx = basec + lane;
            int s1 = 0, e1 = 0, s2 = 0, e2 = 0;
            if (idx < nxy) {
                int dx = idx / n - r, dy = idx % n - r;
                int xx = cx + dx, yy = cy + dy;
                if (xx >= 0 && xx < GG && yy >= 0 && yy < GG) {
                    int cid = cbase + (xx * GG + yy) * GG;
                    int adx = (dx < 0) ? -dx : dx, ady = (dy < 0) ? -dy : dy;
                    if (adx == r || ady == r) {
                        s1 = g_cstart[cid + zlo];
                        e1 = g_cstart[cid + zhi + 1];
                    } else {
                        int z1 = cz - r;
                        if (z1 >= 0) { s1 = g_cstart[cid + z1]; e1 = g_cstart[cid + z1 + 1]; }
                        int z2 = cz + r;
                        if (z2 < GG) { s2 = g_cstart[cid + z2]; e2 = g_cstart[cid + z2 + 1]; }
                    }
                }
            }
            int lim = min(32, nxy - basec);
            for (int c = 0; c < lim; c++) {
                int s = __shfl_sync(FULL, s1, c);
                int e = __shfl_sync(FULL, e1, c);
                if (s < e) scan_range(s, e, lane, qx2, qy2, qz2, qq, kd, ld, li);
                s = __shfl_sync(FULL, s2, c);
                e = __shfl_sync(FULL, e2, c);
                if (s < e) scan_range(s, e, lane, qx2, qy2, qz2, qq, kd, ld, li);
            }
        }
    }

    g_knn[(size_t)qid * KK + lane] = li;
}

// ---------------- distributed warp max-reduce stage ----------------
template <int M, int SH>
__device__ __forceinline__ void redstage(float* o, int l)
{
    int bit = (l >> SH) & 1;
#pragma unroll
    for (int i = 0; i < M; i++) {
        float snd = bit ? o[i] : o[M + i];
        float rcv = __shfl_xor_sync(0xffffffffu, snd, 1 << SH);
        float mine = bit ? o[M + i] : o[i];
        o[i] = fmaxf(mine, rcv);
    }
}

// ---------------- MLP + maxpool: packed f32x2 math ----------------
// fma.rn.f32x2 does two independent IEEE fp32 fma.rn -> bitwise identical
// to the scalar version; accumulation order (c ascending) unchanged.
__global__ void __launch_bounds__(256)
mlp_kernel(const float* __restrict__ xyz, const float* __restrict__ feat,
           const int* __restrict__ sidx,
           const float* __restrict__ w1g, const float* __restrict__ w2g,
           const float* __restrict__ w3g,
           float* __restrict__ out)
{
    __shared__ __align__(16) float sW1[C0 * C1];
    __shared__ __align__(16) float sW2[C1 * C2];
    __shared__ __align__(16) float sW3[C2 * C3];
    __shared__ float sA1[C1], sB1[C1], sA2[C2], sB2[C2], sA3[C3], sB3[C3];
    for (int i = threadIdx.x; i < C0 * C1; i += 256) sW1[i] = w1g[i];
    for (int i = threadIdx.x; i < C1 * C2; i += 256) sW2[i] = w2g[i];
    for (int i = threadIdx.x; i < C2 * C3; i += 256) sW3[i] = w3g[i];
    if (threadIdx.x < C1) { sA1[threadIdx.x] = g_a1[threadIdx.x]; sB1[threadIdx.x] = g_b1[threadIdx.x]; }
    if (threadIdx.x < C2) { sA2[threadIdx.x] = g_a2[threadIdx.x]; sB2[threadIdx.x] = g_b2[threadIdx.x]; }
    if (threadIdx.x < C3) { sA3[threadIdx.x] = g_a3[threadIdx.x]; sB3[threadIdx.x] = g_b3[threadIdx.x]; }
    __syncthreads();

    int warp = threadIdx.x >> 5;
    int lane = threadIdx.x & 31;
    int qid = blockIdx.x * 8 + warp;
    int b = qid >> 12;

    int sid = sidx[qid];
    const float* qp = xyz + ((size_t)b * NN + sid) * 3;
    float qx = qp[0], qy = qp[1], qz = qp[2];

    int nb = g_knn[(size_t)qid * KK + lane];
    const float* pp = xyz + ((size_t)b * NN + nb) * 3;

    float x[C0];
    x[0] = pp[0] - qx;
    x[1] = pp[1] - qy;
    x[2] = pp[2] - qz;
    const float4* f4 = (const float4*)(feat + ((size_t)b * NN + nb) * CINF);
#pragma unroll
    for (int v = 0; v < 4; v++) {
        float4 fv = f4[v];
        x[3 + 4 * v] = fv.x; x[4 + 4 * v] = fv.y;
        x[5 + 4 * v] = fv.z; x[6 + 4 * v] = fv.w;
    }

    // layer 1: 19 -> 32 (16 packed accumulators)
    unsigned long long a1[C1 / 2];
#pragma unroll
    for (int j = 0; j < C1 / 2; j++) a1[j] = 0ull;
    {
        const ulonglong2* Wv = (const ulonglong2*)sW1;
#pragma unroll
        for (int c = 0; c < C0; c++) {
            unsigned long long xp = packf2(x[c]);
#pragma unroll
            for (int q = 0; q < C1 / 4; q++) {
                ulonglong2 wv = Wv[c * (C1 / 4) + q];
                fma2(a1[2 * q + 0], xp, wv.x);
                fma2(a1[2 * q + 1], xp, wv.y);
            }
        }
    }
    float y[C1];
#pragma unroll
    for (int j = 0; j < C1 / 2; j++) unpack2(a1[j], y[2 * j], y[2 * j + 1]);
#pragma unroll
    for (int d = 0; d < C1; d++)
        y[d] = fmaxf(fmaf(y[d], sA1[d], sB1[d]), 0.0f);

    // layer 2: 32 -> 32
    unsigned long long a2[C2 / 2];
#pragma unroll
    for (int j = 0; j < C2 / 2; j++) a2[j] = 0ull;
    {
        const ulonglong2* Wv = (const ulonglong2*)sW2;
#pragma unroll
        for (int c = 0; c < C1; c++) {
            unsigned long long xp = packf2(y[c]);
#pragma unroll
            for (int q = 0; q < C2 / 4; q++) {
                ulonglong2 wv = Wv[c * (C2 / 4) + q];
                fma2(a2[2 * q + 0], xp, wv.x);
                fma2(a2[2 * q + 1], xp, wv.y);
            }
        }
    }
    float z[C2];
#pragma unroll
    for (int j = 0; j < C2 / 2; j++) unpack2(a2[j], z[2 * j], z[2 * j + 1]);
#pragma unroll
    for (int d = 0; d < C2; d++)
        z[d] = fmaxf(fmaf(z[d], sA2[d], sB2[d]), 0.0f);

    // layer 3: 32 -> 64
    unsigned long long a3[C3 / 2];
#pragma unroll
    for (int j = 0; j < C3 / 2; j++) a3[j] = 0ull;
    {
        const ulonglong2* Wv = (const ulonglong2*)sW3;
#pragma unroll
        for (int c = 0; c < C2; c++) {
            unsigned long long xp = packf2(z[c]);
#pragma unroll
            for (int q = 0; q < C3 / 4; q++) {
                ulonglong2 wv = Wv[c * (C3 / 4) + q];
                fma2(a3[2 * q + 0], xp, wv.x);
                fma2(a3[2 * q + 1], xp, wv.y);
            }
        }
    }
    float o[C3];
#pragma unroll
    for (int j = 0; j < C3 / 2; j++) unpack2(a3[j], o[2 * j], o[2 * j + 1]);
#pragma unroll
    for (int d = 0; d < C3; d++)
        o[d] = fmaxf(fmaf(o[d], sA3[d], sB3[d]), 0.0f);

    // max over K=32 neighbors: channel-splitting butterfly.
    redstage<32, 0>(o, lane);
    redstage<16, 1>(o, lane);
    redstage<8,  2>(o, lane);
    redstage<4,  3>(o, lane);
    redstage<2,  4>(o, lane);

    int chb = (((lane >> 0) & 1) << 5) | (((lane >> 1) & 1) << 4) |
              (((lane >> 2) & 1) << 3) | (((lane >> 3) & 1) << 2) |
              (((lane >> 4) & 1) << 1);

    float* dst = out + (size_t)BB * SS * 3 + (size_t)qid * C3 + chb;
    *(float2*)dst = make_float2(o[0], o[1]);
}

// ---------------- launch ----------------
extern "C" void kernel_launch(void* const* d_in, const int* in_sizes, int n_in,
                              void* d_out, int out_size)
{
    const float* xyz     = (const float*)d_in[0];
    const float* feature = (const float*)d_in[1];
    const int*   sidx    = (const int*)d_in[2];

    const float* w0  = (const float*)d_in[3];
    const float* b0  = (const float*)d_in[4];
    const float* g0  = (const float*)d_in[5];
    const float* bt0 = (const float*)d_in[6];
    const float* rm0 = (const float*)d_in[7];
    const float* rv0 = (const float*)d_in[8];
    const float* w1  = (const float*)d_in[9];
    const float* b1  = (const float*)d_in[10];
    const float* g1  = (const float*)d_in[11];
    const float* bt1 = (const float*)d_in[12];
    const float* rm1 = (const float*)d_in[13];
    const float* rv1 = (const float*)d_in[14];
    const float* w2  = (const float*)d_in[15];
    const float* b2  = (const float*)d_in[16];
    const float* g2  = (const float*)d_in[17];
    const float* bt2 = (const float*)d_in[18];
    const float* rm2 = (const float*)d_in[19];
    const float* rv2 = (const float*)d_in[20];

    float* out = (float*)d_out;

    prep_kernel<<<1, 256>>>(b0, g0, bt0, rm0, rv0,
                            b1, g1, bt1, rm1, rv1,
                            b2, g2, bt2, rm2, rv2);
    zero_kernel<<<(BB * NC + 255) / 256, 256>>>();
    count_kernel<<<(BB * NN + 255) / 256, 256>>>(xyz);
    scanB_kernel<<<BB * 32, 1024>>>();
    scanC_kernel<<<1, 128>>>();
    scanD_kernel<<<BB * 32, 1024>>>();
    scatter_kernel<<<(BB * NN + 255) / 256, 256>>>(xyz);
    knn_kernel<<<(BB * SS) / 8, 256>>>(xyz, sidx, out);
    mlp_kernel<<<(BB * SS) / 8, 256>>>(xyz, feature, sidx, w0, w1, w2, out);
}

// round 11
// speedup vs baseline: 2.0601x; 1.0598x over previous
#include <cuda_runtime.h>
#include <cstdint>

#define BB  4
#define NN  16384
#define SS  4096
#define KK  32
#define CINF 16
#define C0  19
#define C1  32
#define C2  32
#define C3  64
#define EPSF 1e-5f

// spatial grid
#define GG     32
#define NC     (GG * GG * GG)
#define BOUNDF 4.5f
#define HH     (9.0f / (float)GG)
#define MARGIN 1e-3f

// ---------------- scratch (no allocs allowed) ----------------
__device__ int    g_knn[BB * SS * KK];
__device__ float  g_a1[C1], g_b1[C1];
__device__ float  g_a2[C2], g_b2[C2];
__device__ float  g_a3[C3], g_b3[C3];

__device__ float4 g_pts[BB * NN];        // cell-sorted (x, y, z, ||p||^2)
__device__ int    g_pidx[BB * NN];       // in-batch original index
__device__ int    g_cell[BB * NN];       // cell id per original point
__device__ int    g_cnt[BB * NC];
__device__ int    g_cstart[BB * NC + 1];
__device__ int    g_ccur[BB * NC];
__device__ int    g_bsum[BB * 32];
__device__ int    g_boff[BB * 32];

// ---------------- packed f32x2 helpers (bitwise == two scalar fma.rn) --------
__device__ __forceinline__ unsigned long long packf2(float v)
{
    unsigned long long r;
    asm("mov.b64 %0, {%1, %1};" : "=l"(r) : "f"(v));
    return r;
}
__device__ __forceinline__ void fma2(unsigned long long& a,
                                     unsigned long long x, unsigned long long w)
{
    asm("fma.rn.f32x2 %0, %1, %2, %0;" : "+l"(a) : "l"(x), "l"(w));
}
__device__ __forceinline__ void unpack2(unsigned long long a, float& lo, float& hi)
{
    asm("mov.b64 {%0, %1}, %2;" : "=f"(lo), "=f"(hi) : "l"(a));
}

// ---------------- prep: fold BN as post-affine ----------------
__global__ void prep_kernel(
    const float* __restrict__ b0,
    const float* __restrict__ g0, const float* __restrict__ bt0,
    const float* __restrict__ rm0, const float* __restrict__ rv0,
    const float* __restrict__ b1,
    const float* __restrict__ g1, const float* __restrict__ bt1,
    const float* __restrict__ rm1, const float* __restrict__ rv1,
    const float* __restrict__ b2,
    const float* __restrict__ g2, const float* __restrict__ bt2,
    const float* __restrict__ rm2, const float* __restrict__ rv2)
{
    int t = threadIdx.x;
    if (t < C1) {
        float A = g0[t] * rsqrtf(rv0[t] + EPSF);
        g_a1[t] = A;
        g_b1[t] = (b0[t] - rm0[t]) * A + bt0[t];
    }
    if (t < C2) {
        float A = g1[t] * rsqrtf(rv1[t] + EPSF);
        g_a2[t] = A;
        g_b2[t] = (b1[t] - rm1[t]) * A + bt1[t];
    }
    if (t < C3) {
        float A = g2[t] * rsqrtf(rv2[t] + EPSF);
        g_a3[t] = A;
        g_b3[t] = (b2[t] - rm2[t]) * A + bt2[t];
    }
}

// ---------------- binning ----------------
__global__ void zero_kernel()
{
    int i = blockIdx.x * blockDim.x + threadIdx.x;
    if (i < BB * NC) g_cnt[i] = 0;
}

__device__ __forceinline__ int clampi(int v) { return min(GG - 1, max(0, v)); }

__device__ __forceinline__ int cell_of(float x, float y, float z)
{
    int cx = clampi((int)floorf((x + BOUNDF) * (1.0f / HH)));
    int cy = clampi((int)floorf((y + BOUNDF) * (1.0f / HH)));
    int cz = clampi((int)floorf((z + BOUNDF) * (1.0f / HH)));
    return (cx * GG + cy) * GG + cz;
}

__global__ void count_kernel(const float* __restrict__ xyz)
{
    int i = blockIdx.x * blockDim.x + threadIdx.x;
    if (i >= BB * NN) return;
    int b = i >> 14;
    const float* p = xyz + (size_t)i * 3;
    int cell = cell_of(p[0], p[1], p[2]);
    g_cell[i] = cell;
    atomicAdd(&g_cnt[b * NC + cell], 1);
}

// hierarchical scan: (B) per-block scans, (C) scan of block sums, (D) add
__global__ void scanB_kernel()   // grid = BB*32, block = 1024, 1 cell/thread
{
    __shared__ int wsum[32];
    const unsigned FULL = 0xffffffffu;
    int t = threadIdx.x, lane = t & 31, w = t >> 5;
    int b = blockIdx.x >> 5, blk = blockIdx.x & 31;
    int cell = blk * 1024 + t;
    int cnt = g_cnt[b * NC + cell];
    int v = cnt;
#pragma unroll
    for (int o = 1; o < 32; o <<= 1) {
        int u = __shfl_up_sync(FULL, v, o);
        if (lane >= o) v += u;
    }
    if (lane == 31) wsum[w] = v;
    __syncthreads();
    if (w == 0) {
        int s = wsum[lane];
#pragma unroll
        for (int o = 1; o < 32; o <<= 1) {
            int u = __shfl_up_sync(FULL, s, o);
            if (lane >= o) s += u;
        }
        wsum[lane] = s;
    }
    __syncthreads();
    int excl = v - cnt + ((w > 0) ? wsum[w - 1] : 0);
    g_cstart[b * NC + cell] = excl;                 // block-local for now
    if (t == 1023) g_bsum[blockIdx.x] = excl + cnt; // block total
}

__global__ void scanC_kernel()   // 1 block, 128 threads; warp w = batch w
{
    const unsigned FULL = 0xffffffffu;
    int lane = threadIdx.x & 31, w = threadIdx.x >> 5;
    int v = g_bsum[w * 32 + lane];
    int inc = v;
#pragma unroll
    for (int o = 1; o < 32; o <<= 1) {
        int u = __shfl_up_sync(FULL, inc, o);
        if (lane >= o) inc += u;
    }
    g_boff[w * 32 + lane] = inc - v + w * NN;
}

__global__ void scanD_kernel()   // grid = BB*32, block = 1024
{
    int b = blockIdx.x >> 5, blk = blockIdx.x & 31;
    int cell = blk * 1024 + threadIdx.x;
    int off = g_boff[blockIdx.x];
    int i = b * NC + cell;
    int v = g_cstart[i] + off;
    g_cstart[i] = v;
    g_ccur[i] = v;
    if (blockIdx.x == 0 && threadIdx.x == 0) g_cstart[BB * NC] = BB * NN;
}

__global__ void scatter_kernel(const float* __restrict__ xyz)
{
    int i = blockIdx.x * blockDim.x + threadIdx.x;
    if (i >= BB * NN) return;
    int b = i >> 14;
    int cell = g_cell[i];
    int pos = atomicAdd(&g_ccur[b * NC + cell], 1);
    const float* p = xyz + (size_t)i * 3;
    float x = p[0], y = p[1], z = p[2];
    float pp = __fadd_rn(__fadd_rn(__fmul_rn(x, x), __fmul_rn(y, y)),
                         __fmul_rn(z, z));
    g_pts[pos] = make_float4(x, y, z, pp);
    g_pidx[pos] = i & (NN - 1);
}

// ---------------- binned KNN: column-segment scans (unchanged) -------
__device__ __forceinline__ void scan_range(
    int s, int e, int lane, float qx2, float qy2, float qz2, float qq,
    float& kd, float& ld, int& li)
{
    const unsigned FULL = 0xffffffffu;
    for (int j = s; j < e; j += 32) {
        int jj = j + lane;
        bool v = jj < e;
        float d = __int_as_float(0x7f800000);
        int ci = 0x7fffffff;
        if (v) {
            float4 p = g_pts[jj];
            ci = g_pidx[jj];
            float dot2 = __fmaf_rn(qz2, p.z,
                         __fmaf_rn(qy2, p.y, __fmul_rn(qx2, p.x)));
            d = __fadd_rn(__fsub_rn(qq, dot2), p.w);
        }
        unsigned m = __ballot_sync(FULL, v && d <= kd);
        if (m) {
            do {
                int src = __ffs(m) - 1;
                m &= m - 1;
                float cd = __shfl_sync(FULL, d, src);
                int   cc = __shfl_sync(FULL, ci, src);
                bool eb = (ld < cd) || (ld == cd && li < cc);
                int pos = __popc(__ballot_sync(FULL, eb));
                float sd = __shfl_up_sync(FULL, ld, 1);
                int   si = __shfl_up_sync(FULL, li, 1);
                if (lane == pos)      { ld = cd; li = cc; }
                else if (lane > pos)  { ld = sd; li = si; }
            } while (m);
            kd = __shfl_sync(FULL, ld, 31);
        }
    }
}

__global__ void __launch_bounds__(256)
knn_kernel(const float* __restrict__ xyz, const int* __restrict__ sidx,
           float* __restrict__ out)
{
    const unsigned FULL = 0xffffffffu;
    int warp = threadIdx.x >> 5;
    int lane = threadIdx.x & 31;
    int qid = blockIdx.x * 8 + warp;
    int b = qid >> 12;

    int sid = sidx[qid];
    const float* qp = xyz + ((size_t)b * NN + sid) * 3;
    float x = qp[0], y = qp[1], z = qp[2];
    float qq = __fadd_rn(__fadd_rn(__fmul_rn(x, x), __fmul_rn(y, y)),
                         __fmul_rn(z, z));
    float qx2 = 2.0f * x, qy2 = 2.0f * y, qz2 = 2.0f * z;

    if (lane == 0) {                                // fold meta outputs
        out[qid * 3 + 0] = x;
        out[qid * 3 + 1] = y;
        out[qid * 3 + 2] = z;
        out[(size_t)BB * SS * 3 + (size_t)BB * SS * C3 + qid] = (float)sid;
    }

    int cx = clampi((int)floorf((x + BOUNDF) * (1.0f / HH)));
    int cy = clampi((int)floorf((y + BOUNDF) * (1.0f / HH)));
    int cz = clampi((int)floorf((z + BOUNDF) * (1.0f / HH)));
    int cbase = b * NC;

    // ---- Phase A: pick starting radius (box count >= 48 or box = grid) ----
    int r = 1;
    for (;; r++) {
        bool full = (cx - r <= 0) && (cx + r >= GG - 1) &&
                    (cy - r <= 0) && (cy + r >= GG - 1) &&
                    (cz - r <= 0) && (cz + r >= GG - 1);
        int n = 2 * r + 1, nxy = n * n;
        int zlo = max(cz - r, 0), zhi = min(cz + r, GG - 1);
        int total = 0;
        for (int basec = 0; basec < nxy; basec += 32) {
            int idx = basec + lane;
            int cnt = 0;
            if (idx < nxy) {
                int xx = cx + idx / n - r, yy = cy + idx % n - r;
                if (xx >= 0 && xx < GG && yy >= 0 && yy < GG) {
                    int cid = cbase + (xx * GG + yy) * GG;
                    cnt = g_cstart[cid + zhi + 1] - g_cstart[cid + zlo];
                }
            }
#pragma unroll
            for (int o = 16; o; o >>= 1) cnt += __shfl_xor_sync(FULL, cnt, o);
            total += cnt;
        }
        if (total >= 48 || full) break;
    }

    float ld = __int_as_float(0x7f800000);
    int   li = 0x7fffffff;
    float kd = ld;

    // ---- Phase B: scan box radius r as column segments ----
    {
        int n = 2 * r + 1, nxy = n * n;
        int zlo = max(cz - r, 0), zhi = min(cz + r, GG - 1);
        for (int basec = 0; basec < nxy; basec += 32) {
            int idx = basec + lane;
            int s0 = 0, e0 = 0;
            if (idx < nxy) {
                int xx = cx + idx / n - r, yy = cy + idx % n - r;
                if (xx >= 0 && xx < GG && yy >= 0 && yy < GG) {
                    int cid = cbase + (xx * GG + yy) * GG;
                    s0 = g_cstart[cid + zlo];
                    e0 = g_cstart[cid + zhi + 1];
                }
            }
            int lim = min(32, nxy - basec);
            for (int c = 0; c < lim; c++) {
                int s = __shfl_sync(FULL, s0, c);
                int e = __shfl_sync(FULL, e0, c);
                if (s < e) scan_range(s, e, lane, qx2, qy2, qz2, qq, kd, ld, li);
            }
        }
    }

    // ---- expand shells until safety bound holds ----
    for (;;) {
        bool full = (cx - r <= 0) && (cx + r >= GG - 1) &&
                    (cy - r <= 0) && (cy + r >= GG - 1) &&
                    (cz - r <= 0) && (cz + r >= GG - 1);
        float rb = (float)r * HH;
        if (full || kd < rb * rb - MARGIN) break;
        r++;
        int n = 2 * r + 1, nxy = n * n;
        int zlo = max(cz - r, 0), zhi = min(cz + r, GG - 1);
        for (int basec = 0; basec < nxy; basec += 32) {
            int idx = basec + lane;
            int s1 = 0, e1 = 0, s2 = 0, e2 = 0;
            if (idx < nxy) {
                int dx = idx / n - r, dy = idx % n - r;
                int xx = cx + dx, yy = cy + dy;
                if (xx >= 0 && xx < GG && yy >= 0 && yy < GG) {
                    int cid = cbase + (xx * GG + yy) * GG;
                    int adx = (dx < 0) ? -dx : dx, ady = (dy < 0) ? -dy : dy;
                    if (adx == r || ady == r) {
                        s1 = g_cstart[cid + zlo];
                        e1 = g_cstart[cid + zhi + 1];
                    } else {
                        int z1 = cz - r;
                        if (z1 >= 0) { s1 = g_cstart[cid + z1]; e1 = g_cstart[cid + z1 + 1]; }
                        int z2 = cz + r;
                        if (z2 < GG) { s2 = g_cstart[cid + z2]; e2 = g_cstart[cid + z2 + 1]; }
                    }
                }
            }
            int lim = min(32, nxy - basec);
            for (int c = 0; c < lim; c++) {
                int s = __shfl_sync(FULL, s1, c);
                int e = __shfl_sync(FULL, e1, c);
                if (s < e) scan_range(s, e, lane, qx2, qy2, qz2, qq, kd, ld, li);
                s = __shfl_sync(FULL, s2, c);
                e = __shfl_sync(FULL, e2, c);
                if (s < e) scan_range(s, e, lane, qx2, qy2, qz2, qq, kd, ld, li);
            }
        }
    }

    g_knn[(size_t)qid * KK + lane] = li;
}

// ---------------- distributed warp max-reduce stage ----------------
template <int M, int SH>
__device__ __forceinline__ void redstage(float* o, int l)
{
    int bit = (l >> SH) & 1;
#pragma unroll
    for (int i = 0; i < M; i++) {
        float snd = bit ? o[i] : o[M + i];
        float rcv = __shfl_xor_sync(0xffffffffu, snd, 1 << SH);
        float mine = bit ? o[M + i] : o[i];
        o[i] = fmaxf(mine, rcv);
    }
}

// ---------------- MLP + maxpool: f32x2 with 2-blocks/SM guaranteed ----------
// fma.rn.f32x2 does two independent IEEE fp32 fma.rn -> bitwise identical.
// Layer 3 computed in two 32-channel passes to keep regs <= 128 so that
// __launch_bounds__(256, 2) holds 16 warps/SM resident.
__global__ void __launch_bounds__(256, 2)
mlp_kernel(const float* __restrict__ xyz, const float* __restrict__ feat,
           const int* __restrict__ sidx,
           const float* __restrict__ w1g, const float* __restrict__ w2g,
           const float* __restrict__ w3g,
           float* __restrict__ out)
{
    __shared__ __align__(16) float sW1[C0 * C1];
    __shared__ __align__(16) float sW2[C1 * C2];
    __shared__ __align__(16) float sW3[C2 * C3];
    __shared__ float sA1[C1], sB1[C1], sA2[C2], sB2[C2], sA3[C3], sB3[C3];
    for (int i = threadIdx.x; i < C0 * C1; i += 256) sW1[i] = w1g[i];
    for (int i = threadIdx.x; i < C1 * C2; i += 256) sW2[i] = w2g[i];
    for (int i = threadIdx.x; i < C2 * C3; i += 256) sW3[i] = w3g[i];
    if (threadIdx.x < C1) { sA1[threadIdx.x] = g_a1[threadIdx.x]; sB1[threadIdx.x] = g_b1[threadIdx.x]; }
    if (threadIdx.x < C2) { sA2[threadIdx.x] = g_a2[threadIdx.x]; sB2[threadIdx.x] = g_b2[threadIdx.x]; }
    if (threadIdx.x < C3) { sA3[threadIdx.x] = g_a3[threadIdx.x]; sB3[threadIdx.x] = g_b3[threadIdx.x]; }
    __syncthreads();

    int warp = threadIdx.x >> 5;
    int lane = threadIdx.x & 31;
    int qid = blockIdx.x * 8 + warp;
    int b = qid >> 12;

    int sid = sidx[qid];
    const float* qp = xyz + ((size_t)b * NN + sid) * 3;
    float qx = qp[0], qy = qp[1], qz = qp[2];

    int nb = g_knn[(size_t)qid * KK + lane];
    const float* pp = xyz + ((size_t)b * NN + nb) * 3;

    float x[C0];
    x[0] = pp[0] - qx;
    x[1] = pp[1] - qy;
    x[2] = pp[2] - qz;
    const float4* f4 = (const float4*)(feat + ((size_t)b * NN + nb) * CINF);
#pragma unroll
    for (int v = 0; v < 4; v++) {
        float4 fv = f4[v];
        x[3 + 4 * v] = fv.x; x[4 + 4 * v] = fv.y;
        x[5 + 4 * v] = fv.z; x[6 + 4 * v] = fv.w;
    }

    // layer 1: 19 -> 32 (16 packed accumulators)
    unsigned long long a1[C1 / 2];
#pragma unroll
    for (int j = 0; j < C1 / 2; j++) a1[j] = 0ull;
    {
        const ulonglong2* Wv = (const ulonglong2*)sW1;
#pragma unroll
        for (int c = 0; c < C0; c++) {
            unsigned long long xp = packf2(x[c]);
#pragma unroll
            for (int q = 0; q < C1 / 4; q++) {
                ulonglong2 wv = Wv[c * (C1 / 4) + q];
                fma2(a1[2 * q + 0], xp, wv.x);
                fma2(a1[2 * q + 1], xp, wv.y);
            }
        }
    }
    float y[C1];
#pragma unroll
    for (int j = 0; j < C1 / 2; j++) unpack2(a1[j], y[2 * j], y[2 * j + 1]);
#pragma unroll
    for (int d = 0; d < C1; d++)
        y[d] = fmaxf(fmaf(y[d], sA1[d], sB1[d]), 0.0f);

    // layer 2: 32 -> 32
    unsigned long long a2[C2 / 2];
#pragma unroll
    for (int j = 0; j < C2 / 2; j++) a2[j] = 0ull;
    {
        const ulonglong2* Wv = (const ulonglong2*)sW2;
#pragma unroll
        for (int c = 0; c < C1; c++) {
            unsigned long long xp = packf2(y[c]);
#pragma unroll
            for (int q = 0; q < C2 / 4; q++) {
                ulonglong2 wv = Wv[c * (C2 / 4) + q];
                fma2(a2[2 * q + 0], xp, wv.x);
                fma2(a2[2 * q + 1], xp, wv.y);
            }
        }
    }
    float z[C2];
#pragma unroll
    for (int j = 0; j < C2 / 2; j++) unpack2(a2[j], z[2 * j], z[2 * j + 1]);
#pragma unroll
    for (int d = 0; d < C2; d++)
        z[d] = fmaxf(fmaf(z[d], sA2[d], sB2[d]), 0.0f);

    // layer 3: 32 -> 64 in two 32-channel passes (keeps regs <= 128)
    float o[C3];
    const ulonglong2* Wv3 = (const ulonglong2*)sW3;   // 16 ulonglong2 per row
#pragma unroll
    for (int half = 0; half < 2; half++) {
        unsigned long long a3[16];
#pragma unroll
        for (int j = 0; j < 16; j++) a3[j] = 0ull;
#pragma unroll
        for (int c = 0; c < C2; c++) {
            unsigned long long xp = packf2(z[c]);
#pragma unroll
            for (int q = 0; q < 8; q++) {
                ulonglong2 wv = Wv3[c * 16 + half * 8 + q];
                fma2(a3[2 * q + 0], xp, wv.x);
                fma2(a3[2 * q + 1], xp, wv.y);
            }
        }
#pragma unroll
        for (int j = 0; j < 16; j++)
            unpack2(a3[j], o[half * 32 + 2 * j], o[half * 32 + 2 * j + 1]);
    }
#pragma unroll
    for (int d = 0; d < C3; d++)
        o[d] = fmaxf(fmaf(o[d], sA3[d], sB3[d]), 0.0f);

    // max over K=32 neighbors: channel-splitting butterfly.
    redstage<32, 0>(o, lane);
    redstage<16, 1>(o, lane);
    redstage<8,  2>(o, lane);
    redstage<4,  3>(o, lane);
    redstage<2,  4>(o, lane);

    int chb = (((lane >> 0) & 1) << 5) | (((lane >> 1) & 1) << 4) |
              (((lane >> 2) & 1) << 3) | (((lane >> 3) & 1) << 2) |
              (((lane >> 4) & 1) << 1);

    float* dst = out + (size_t)BB * SS * 3 + (size_t)qid * C3 + chb;
    *(float2*)dst = make_float2(o[0], o[1]);
}

// ---------------- launch ----------------
extern "C" void kernel_launch(void* const* d_in, const int* in_sizes, int n_in,
                              void* d_out, int out_size)
{
    const float* xyz     = (const float*)d_in[0];
    const float* feature = (const float*)d_in[1];
    const int*   sidx    = (const int*)d_in[2];

    const float* w0  = (const float*)d_in[3];
    const float* b0  = (const float*)d_in[4];
    const float* g0  = (const float*)d_in[5];
    const float* bt0 = (const float*)d_in[6];
    const float* rm0 = (const float*)d_in[7];
    const float* rv0 = (const float*)d_in[8];
    const float* w1  = (const float*)d_in[9];
    const float* b1  = (const float*)d_in[10];
    const float* g1  = (const float*)d_in[11];
    const float* bt1 = (const float*)d_in[12];
    const float* rm1 = (const float*)d_in[13];
    const float* rv1 = (const float*)d_in[14];
    const float* w2  = (const float*)d_in[15];
    const float* b2  = (const float*)d_in[16];
    const float* g2  = (const float*)d_in[17];
    const float* bt2 = (const float*)d_in[18];
    const float* rm2 = (const float*)d_in[19];
    const float* rv2 = (const float*)d_in[20];

    float* out = (float*)d_out;

    prep_kernel<<<1, 256>>>(b0, g0, bt0, rm0, rv0,
                            b1, g1, bt1, rm1, rv1,
                            b2, g2, bt2, rm2, rv2);
    zero_kernel<<<(BB * NC + 255) / 256, 256>>>();
    count_kernel<<<(BB * NN + 255) / 256, 256>>>(xyz);
    scanB_kernel<<<BB * 32, 1024>>>();
    scanC_kernel<<<1, 128>>>();
    scanD_kernel<<<BB * 32, 1024>>>();
    scatter_kernel<<<(BB * NN + 255) / 256, 256>>>(xyz);
    knn_kernel<<<(BB * SS) / 8, 256>>>(xyz, sidx, out);
    mlp_kernel<<<(BB * SS) / 8, 256>>>(xyz, feature, sidx, w0, w1, w2, out);
}

// round 12
// speedup vs baseline: 2.8315x; 1.3745x over previous
#include <cuda_runtime.h>
#include <cstdint>

#define BB  4
#define NN  16384
#define SS  4096
#define KK  32
#define CINF 16
#define C0  19
#define C1  32
#define C2  32
#define C3  64
#define EPSF 1e-5f

// spatial grid
#define GG     32
#define NC     (GG * GG * GG)
#define BOUNDF 4.5f
#define HH     (9.0f / (float)GG)
#define MARGIN 1e-3f

#define FINF __int_as_float(0x7f800000)

// ---------------- scratch (no allocs allowed) ----------------
__device__ int    g_knn[BB * SS * KK];
__device__ float  g_a1[C1], g_b1[C1];
__device__ float  g_a2[C2], g_b2[C2];
__device__ float  g_a3[C3], g_b3[C3];

__device__ float4 g_pts[BB * NN];        // cell-sorted (x, y, z, ||p||^2)
__device__ int    g_pidx[BB * NN];       // in-batch original index
__device__ int    g_cell[BB * NN];       // cell id per original point
__device__ int    g_cnt[BB * NC];
__device__ int    g_cstart[BB * NC + 1];
__device__ int    g_ccur[BB * NC];
__device__ int    g_bsum[BB * 32];
__device__ int    g_boff[BB * 32];

// ---------------- packed f32x2 helpers (bitwise == two scalar fma.rn) --------
__device__ __forceinline__ unsigned long long packf2(float v)
{
    unsigned long long r;
    asm("mov.b64 %0, {%1, %1};" : "=l"(r) : "f"(v));
    return r;
}
__device__ __forceinline__ void fma2(unsigned long long& a,
                                     unsigned long long x, unsigned long long w)
{
    asm("fma.rn.f32x2 %0, %1, %2, %0;" : "+l"(a) : "l"(x), "l"(w));
}
__device__ __forceinline__ void unpack2(unsigned long long a, float& lo, float& hi)
{
    asm("mov.b64 {%0, %1}, %2;" : "=f"(lo), "=f"(hi) : "l"(a));
}

// ---------------- prep: fold BN as post-affine ----------------
__global__ void prep_kernel(
    const float* __restrict__ b0,
    const float* __restrict__ g0, const float* __restrict__ bt0,
    const float* __restrict__ rm0, const float* __restrict__ rv0,
    const float* __restrict__ b1,
    const float* __restrict__ g1, const float* __restrict__ bt1,
    const float* __restrict__ rm1, const float* __restrict__ rv1,
    const float* __restrict__ b2,
    const float* __restrict__ g2, const float* __restrict__ bt2,
    const float* __restrict__ rm2, const float* __restrict__ rv2)
{
    int t = threadIdx.x;
    if (t < C1) {
        float A = g0[t] * rsqrtf(rv0[t] + EPSF);
        g_a1[t] = A;
        g_b1[t] = (b0[t] - rm0[t]) * A + bt0[t];
    }
    if (t < C2) {
        float A = g1[t] * rsqrtf(rv1[t] + EPSF);
        g_a2[t] = A;
        g_b2[t] = (b1[t] - rm1[t]) * A + bt1[t];
    }
    if (t < C3) {
        float A = g2[t] * rsqrtf(rv2[t] + EPSF);
        g_a3[t] = A;
        g_b3[t] = (b2[t] - rm2[t]) * A + bt2[t];
    }
}

// ---------------- binning ----------------
__global__ void zero_kernel()
{
    int i = blockIdx.x * blockDim.x + threadIdx.x;
    if (i < BB * NC) g_cnt[i] = 0;
}

__device__ __forceinline__ int clampi(int v) { return min(GG - 1, max(0, v)); }

__device__ __forceinline__ int cell_of(float x, float y, float z)
{
    int cx = clampi((int)floorf((x + BOUNDF) * (1.0f / HH)));
    int cy = clampi((int)floorf((y + BOUNDF) * (1.0f / HH)));
    int cz = clampi((int)floorf((z + BOUNDF) * (1.0f / HH)));
    return (cx * GG + cy) * GG + cz;
}

__global__ void count_kernel(const float* __restrict__ xyz)
{
    int i = blockIdx.x * blockDim.x + threadIdx.x;
    if (i >= BB * NN) return;
    int b = i >> 14;
    const float* p = xyz + (size_t)i * 3;
    int cell = cell_of(p[0], p[1], p[2]);
    g_cell[i] = cell;
    atomicAdd(&g_cnt[b * NC + cell], 1);
}

// hierarchical scan: (B) per-block scans, (C) scan of block sums, (D) add
__global__ void scanB_kernel()   // grid = BB*32, block = 1024, 1 cell/thread
{
    __shared__ int wsum[32];
    const unsigned FULL = 0xffffffffu;
    int t = threadIdx.x, lane = t & 31, w = t >> 5;
    int b = blockIdx.x >> 5, blk = blockIdx.x & 31;
    int cell = blk * 1024 + t;
    int cnt = g_cnt[b * NC + cell];
    int v = cnt;
#pragma unroll
    for (int o = 1; o < 32; o <<= 1) {
        int u = __shfl_up_sync(FULL, v, o);
        if (lane >= o) v += u;
    }
    if (lane == 31) wsum[w] = v;
    __syncthreads();
    if (w == 0) {
        int s = wsum[lane];
#pragma unroll
        for (int o = 1; o < 32; o <<= 1) {
            int u = __shfl_up_sync(FULL, s, o);
            if (lane >= o) s += u;
        }
        wsum[lane] = s;
    }
    __syncthreads();
    int excl = v - cnt + ((w > 0) ? wsum[w - 1] : 0);
    g_cstart[b * NC + cell] = excl;                 // block-local for now
    if (t == 1023) g_bsum[blockIdx.x] = excl + cnt; // block total
}

__global__ void scanC_kernel()   // 1 block, 128 threads; warp w = batch w
{
    const unsigned FULL = 0xffffffffu;
    int lane = threadIdx.x & 31, w = threadIdx.x >> 5;
    int v = g_bsum[w * 32 + lane];
    int inc = v;
#pragma unroll
    for (int o = 1; o < 32; o <<= 1) {
        int u = __shfl_up_sync(FULL, inc, o);
        if (lane >= o) inc += u;
    }
    g_boff[w * 32 + lane] = inc - v + w * NN;
}

__global__ void scanD_kernel()   // grid = BB*32, block = 1024
{
    int b = blockIdx.x >> 5, blk = blockIdx.x & 31;
    int cell = blk * 1024 + threadIdx.x;
    int off = g_boff[blockIdx.x];
    int i = b * NC + cell;
    int v = g_cstart[i] + off;
    g_cstart[i] = v;
    g_ccur[i] = v;
    if (blockIdx.x == 0 && threadIdx.x == 0) g_cstart[BB * NC] = BB * NN;
}

__global__ void scatter_kernel(const float* __restrict__ xyz)
{
    int i = blockIdx.x * blockDim.x + threadIdx.x;
    if (i >= BB * NN) return;
    int b = i >> 14;
    int cell = g_cell[i];
    int pos = atomicAdd(&g_ccur[b * NC + cell], 1);
    const float* p = xyz + (size_t)i * 3;
    float x = p[0], y = p[1], z = p[2];
    float pp = __fadd_rn(__fadd_rn(__fmul_rn(x, x), __fmul_rn(y, y)),
                         __fmul_rn(z, z));
    g_pts[pos] = make_float4(x, y, z, pp);
    g_pidx[pos] = i & (NN - 1);
}

// ---------------- binned KNN v3: flattened group scans + bitonic init --------
// Distances bitwise-identical to R5..R11 (validated):
//   qq, pp : (x*x + y*y) + z*z, mul+add, NO fma
//   dot2   : fma(2qz,pz, fma(2qy,py, rn(2qx*px))) == 2*dot bitwise
//   d      : (qq - dot2) + pp, NO fma
// Warp-distributed sorted top-32 of (d, idx); order-independent result.
__device__ __forceinline__ bool lessdi(float d1, int i1, float d2, int i2)
{
    return (d1 < d2) || (d1 == d2 && i1 < i2);
}

// Scan a group of up to 32 per-lane segments [s0,e0), flattened so every
// chunk of 32 candidates fills all lanes. virgin: list untouched; first full
// chunk is bitonic-sorted straight into the distributed list.
__device__ void scan_group_flat(
    int s0, int e0, int lane, float qx2, float qy2, float qz2, float qq,
    float& kd, float& ld, int& li, bool& virgin)
{
    const unsigned FULL = 0xffffffffu;
    int len = max(e0 - s0, 0);
    int off = len;
#pragma unroll
    for (int o = 1; o < 32; o <<= 1) {
        int u = __shfl_up_sync(FULL, off, o);
        if (lane >= o) off += u;
    }
    int total = __shfl_sync(FULL, off, 31);
    off -= len;                                    // exclusive prefix

    for (int g0 = 0; g0 < total; g0 += 32) {
        int g = g0 + lane;
        bool v = g < total;
        // binary search: largest c with off[c] <= g (per-lane src shfl)
        int c = 0;
#pragma unroll
        for (int step = 16; step; step >>= 1) {
            int cand = c + step;
            int oc = __shfl_sync(FULL, off, cand);
            if (v && oc <= g) c = cand;
        }
        int sc = __shfl_sync(FULL, s0, c);
        int oc = __shfl_sync(FULL, off, c);
        float d = FINF;
        int ci = 0x7fffffff;
        if (v) {
            int jj = sc + (g - oc);
            float4 p = g_pts[jj];
            ci = g_pidx[jj];
            float dot2 = __fmaf_rn(qz2, p.z,
                         __fmaf_rn(qy2, p.y, __fmul_rn(qx2, p.x)));
            d = __fadd_rn(__fsub_rn(qq, dot2), p.w);
        }
        if (virgin && (total - g0 >= 32)) {
            // bitonic sort the full chunk ascending by (d, idx) -> the list
#pragma unroll
            for (int k = 2; k <= 32; k <<= 1) {
#pragma unroll
                for (int j = k >> 1; j > 0; j >>= 1) {
                    float d2 = __shfl_xor_sync(FULL, d, j);
                    int   i2 = __shfl_xor_sync(FULL, ci, j);
                    bool keepmin = (((lane & j) == 0) == ((lane & k) == 0));
                    bool pless = lessdi(d2, i2, d, ci);
                    if (keepmin == pless) { d = d2; ci = i2; }
                }
            }
            ld = d; li = ci;
            kd = __shfl_sync(FULL, ld, 31);
            virgin = false;
            continue;
        }
        unsigned m = __ballot_sync(FULL, v && d <= kd);
        if (m) {
            do {
                int src = __ffs(m) - 1;
                m &= m - 1;
                float cd = __shfl_sync(FULL, d, src);
                int   cc = __shfl_sync(FULL, ci, src);
                bool eb = lessdi(ld, li, cd, cc);
                int pos = __popc(__ballot_sync(FULL, eb));
                float sd = __shfl_up_sync(FULL, ld, 1);
                int   si = __shfl_up_sync(FULL, li, 1);
                if (lane == pos)      { ld = cd; li = cc; }
                else if (lane > pos)  { ld = sd; li = si; }
            } while (m);
            kd = __shfl_sync(FULL, ld, 31);
        }
        virgin = false;
    }
}

__global__ void __launch_bounds__(256)
knn_kernel(const float* __restrict__ xyz, const int* __restrict__ sidx,
           float* __restrict__ out)
{
    const unsigned FULL = 0xffffffffu;
    int warp = threadIdx.x >> 5;
    int lane = threadIdx.x & 31;
    int qid = blockIdx.x * 8 + warp;
    int b = qid >> 12;

    int sid = sidx[qid];
    const float* qp = xyz + ((size_t)b * NN + sid) * 3;
    float x = qp[0], y = qp[1], z = qp[2];
    float qq = __fadd_rn(__fadd_rn(__fmul_rn(x, x), __fmul_rn(y, y)),
                         __fmul_rn(z, z));
    float qx2 = 2.0f * x, qy2 = 2.0f * y, qz2 = 2.0f * z;

    if (lane == 0) {                                // fold meta outputs
        out[qid * 3 + 0] = x;
        out[qid * 3 + 1] = y;
        out[qid * 3 + 2] = z;
        out[(size_t)BB * SS * 3 + (size_t)BB * SS * C3 + qid] = (float)sid;
    }

    int cx = clampi((int)floorf((x + BOUNDF) * (1.0f / HH)));
    int cy = clampi((int)floorf((y + BOUNDF) * (1.0f / HH)));
    int cz = clampi((int)floorf((z + BOUNDF) * (1.0f / HH)));
    int cbase = b * NC;

    // ---- Phase A: pick starting radius (box count >= 48 or box = grid) ----
    int r = 1;
    for (;; r++) {
        bool full = (cx - r <= 0) && (cx + r >= GG - 1) &&
                    (cy - r <= 0) && (cy + r >= GG - 1) &&
                    (cz - r <= 0) && (cz + r >= GG - 1);
        int n = 2 * r + 1, nxy = n * n;
        int zlo = max(cz - r, 0), zhi = min(cz + r, GG - 1);
        int total = 0;
        for (int basec = 0; basec < nxy; basec += 32) {
            int idx = basec + lane;
            int cnt = 0;
            if (idx < nxy) {
                int xx = cx + idx / n - r, yy = cy + idx % n - r;
                if (xx >= 0 && xx < GG && yy >= 0 && yy < GG) {
                    int cid = cbase + (xx * GG + yy) * GG;
                    cnt = g_cstart[cid + zhi + 1] - g_cstart[cid + zlo];
                }
            }
#pragma unroll
            for (int o = 16; o; o >>= 1) cnt += __shfl_xor_sync(FULL, cnt, o);
            total += cnt;
        }
        if (total >= 48 || full) break;
    }

    float ld = FINF;
    int   li = 0x7fffffff;
    float kd = ld;
    bool  virgin = true;

    // ---- Phase B: flattened scan of the radius-r box ----
    {
        int n = 2 * r + 1, nxy = n * n;
        int zlo = max(cz - r, 0), zhi = min(cz + r, GG - 1);
        for (int basec = 0; basec < nxy; basec += 32) {
            int idx = basec + lane;
            int s0 = 0, e0 = 0;
            if (idx < nxy) {
                int xx = cx + idx / n - r, yy = cy + idx % n - r;
                if (xx >= 0 && xx < GG && yy >= 0 && yy < GG) {
                    int cid = cbase + (xx * GG + yy) * GG;
                    s0 = g_cstart[cid + zlo];
                    e0 = g_cstart[cid + zhi + 1];
                }
            }
            scan_group_flat(s0, e0, lane, qx2, qy2, qz2, qq, kd, ld, li, virgin);
        }
    }

    // ---- expand shells until safety bound holds ----
    for (;;) {
        bool full = (cx - r <= 0) && (cx + r >= GG - 1) &&
                    (cy - r <= 0) && (cy + r >= GG - 1) &&
                    (cz - r <= 0) && (cz + r >= GG - 1);
        float rb = (float)r * HH;
        if (full || kd < rb * rb - MARGIN) break;
        r++;
        int n = 2 * r + 1, nxy = n * n;
        int zlo = max(cz - r, 0), zhi = min(cz + r, GG - 1);
        for (int basec = 0; basec < nxy; basec += 32) {
            int idx = basec + lane;
            int s1 = 0, e1 = 0, s2 = 0, e2 = 0;
            if (idx < nxy) {
                int dx = idx / n - r, dy = idx % n - r;
                int xx = cx + dx, yy = cy + dy;
                if (xx >= 0 && xx < GG && yy >= 0 && yy < GG) {
                    int cid = cbase + (xx * GG + yy) * GG;
                    int adx = (dx < 0) ? -dx : dx, ady = (dy < 0) ? -dy : dy;
                    if (adx == r || ady == r) {          // new perimeter column
                        s1 = g_cstart[cid + zlo];
                        e1 = g_cstart[cid + zhi + 1];
                    } else {                              // two new z cells
                        int z1 = cz - r;
                        if (z1 >= 0) { s1 = g_cstart[cid + z1]; e1 = g_cstart[cid + z1 + 1]; }
                        int z2 = cz + r;
                        if (z2 < GG) { s2 = g_cstart[cid + z2]; e2 = g_cstart[cid + z2 + 1]; }
                    }
                }
            }
            scan_group_flat(s1, e1, lane, qx2, qy2, qz2, qq, kd, ld, li, virgin);
            scan_group_flat(s2, e2, lane, qx2, qy2, qz2, qq, kd, ld, li, virgin);
        }
    }

    g_knn[(size_t)qid * KK + lane] = li;
}

// ---------------- distributed warp max-reduce stage ----------------
template <int M, int SH>
__device__ __forceinline__ void redstage(float* o, int l)
{
    int bit = (l >> SH) & 1;
#pragma unroll
    for (int i = 0; i < M; i++) {
        float snd = bit ? o[i] : o[M + i];
        float rcv = __shfl_xor_sync(0xffffffffu, snd, 1 << SH);
        float mine = bit ? o[M + i] : o[i];
        o[i] = fmaxf(mine, rcv);
    }
}

// ---------------- MLP + maxpool: f32x2 with 2-blocks/SM guaranteed ----------
__global__ void __launch_bounds__(256, 2)
mlp_kernel(const float* __restrict__ xyz, const float* __restrict__ feat,
           const int* __restrict__ sidx,
           const float* __restrict__ w1g, const float* __restrict__ w2g,
           const float* __restrict__ w3g,
           float* __restrict__ out)
{
    __shared__ __align__(16) float sW1[C0 * C1];
    __shared__ __align__(16) float sW2[C1 * C2];
    __shared__ __align__(16) float sW3[C2 * C3];
    __shared__ float sA1[C1], sB1[C1], sA2[C2], sB2[C2], sA3[C3], sB3[C3];
    for (int i = threadIdx.x; i < C0 * C1; i += 256) sW1[i] = w1g[i];
    for (int i = threadIdx.x; i < C1 * C2; i += 256) sW2[i] = w2g[i];
    for (int i = threadIdx.x; i < C2 * C3; i += 256) sW3[i] = w3g[i];
    if (threadIdx.x < C1) { sA1[threadIdx.x] = g_a1[threadIdx.x]; sB1[threadIdx.x] = g_b1[threadIdx.x]; }
    if (threadIdx.x < C2) { sA2[threadIdx.x] = g_a2[threadIdx.x]; sB2[threadIdx.x] = g_b2[threadIdx.x]; }
    if (threadIdx.x < C3) { sA3[threadIdx.x] = g_a3[threadIdx.x]; sB3[threadIdx.x] = g_b3[threadIdx.x]; }
    __syncthreads();

    int warp = threadIdx.x >> 5;
    int lane = threadIdx.x & 31;
    int qid = blockIdx.x * 8 + warp;
    int b = qid >> 12;

    int sid = sidx[qid];
    const float* qp = xyz + ((size_t)b * NN + sid) * 3;
    float qx = qp[0], qy = qp[1], qz = qp[2];

    int nb = g_knn[(size_t)qid * KK + lane];
    const float* pp = xyz + ((size_t)b * NN + nb) * 3;

    float x[C0];
    x[0] = pp[0] - qx;
    x[1] = pp[1] - qy;
    x[2] = pp[2] - qz;
    const float4* f4 = (const float4*)(feat + ((size_t)b * NN + nb) * CINF);
#pragma unroll
    for (int v = 0; v < 4; v++) {
        float4 fv = f4[v];
        x[3 + 4 * v] = fv.x; x[4 + 4 * v] = fv.y;
        x[5 + 4 * v] = fv.z; x[6 + 4 * v] = fv.w;
    }

    // layer 1: 19 -> 32 (16 packed accumulators)
    unsigned long long a1[C1 / 2];
#pragma unroll
    for (int j = 0; j < C1 / 2; j++) a1[j] = 0ull;
    {
        const ulonglong2* Wv = (const ulonglong2*)sW1;
#pragma unroll
        for (int c = 0; c < C0; c++) {
            unsigned long long xp = packf2(x[c]);
#pragma unroll
            for (int q = 0; q < C1 / 4; q++) {
                ulonglong2 wv = Wv[c * (C1 / 4) + q];
                fma2(a1[2 * q + 0], xp, wv.x);
                fma2(a1[2 * q + 1], xp, wv.y);
            }
        }
    }
    float y[C1];
#pragma unroll
    for (int j = 0; j < C1 / 2; j++) unpack2(a1[j], y[2 * j], y[2 * j + 1]);
#pragma unroll
    for (int d = 0; d < C1; d++)
        y[d] = fmaxf(fmaf(y[d], sA1[d], sB1[d]), 0.0f);

    // layer 2: 32 -> 32
    unsigned long long a2[C2 / 2];
#pragma unroll
    for (int j = 0; j < C2 / 2; j++) a2[j] = 0ull;
    {
        const ulonglong2* Wv = (const ulonglong2*)sW2;
#pragma unroll
        for (int c = 0; c < C1; c++) {
            unsigned long long xp = packf2(y[c]);
#pragma unroll
            for (int q = 0; q < C2 / 4; q++) {
                ulonglong2 wv = Wv[c * (C2 / 4) + q];
                fma2(a2[2 * q + 0], xp, wv.x);
                fma2(a2[2 * q + 1], xp, wv.y);
            }
        }
    }
    float z[C2];
#pragma unroll
    for (int j = 0; j < C2 / 2; j++) unpack2(a2[j], z[2 * j], z[2 * j + 1]);
#pragma unroll
    for (int d = 0; d < C2; d++)
        z[d] = fmaxf(fmaf(z[d], sA2[d], sB2[d]), 0.0f);

    // layer 3: 32 -> 64 in two 32-channel passes (keeps regs <= 128)
    float o[C3];
    const ulonglong2* Wv3 = (const ulonglong2*)sW3;   // 16 ulonglong2 per row
#pragma unroll
    for (int half = 0; half < 2; half++) {
        unsigned long long a3[16];
#pragma unroll
        for (int j = 0; j < 16; j++) a3[j] = 0ull;
#pragma unroll
        for (int c = 0; c < C2; c++) {
            unsigned long long xp = packf2(z[c]);
#pragma unroll
            for (int q = 0; q < 8; q++) {
                ulonglong2 wv = Wv3[c * 16 + half * 8 + q];
                fma2(a3[2 * q + 0], xp, wv.x);
                fma2(a3[2 * q + 1], xp, wv.y);
            }
        }
#pragma unroll
        for (int j = 0; j < 16; j++)
            unpack2(a3[j], o[half * 32 + 2 * j], o[half * 32 + 2 * j + 1]);
    }
#pragma unroll
    for (int d = 0; d < C3; d++)
        o[d] = fmaxf(fmaf(o[d], sA3[d], sB3[d]), 0.0f);

    // max over K=32 neighbors: channel-splitting butterfly.
    redstage<32, 0>(o, lane);
    redstage<16, 1>(o, lane);
    redstage<8,  2>(o, lane);
    redstage<4,  3>(o, lane);
    redstage<2,  4>(o, lane);

    int chb = (((lane >> 0) & 1) << 5) | (((lane >> 1) & 1) << 4) |
              (((lane >> 2) & 1) << 3) | (((lane >> 3) & 1) << 2) |
              (((lane >> 4) & 1) << 1);

    float* dst = out + (size_t)BB * SS * 3 + (size_t)qid * C3 + chb;
    *(float2*)dst = make_float2(o[0], o[1]);
}

// ---------------- launch ----------------
extern "C" void kernel_launch(void* const* d_in, const int* in_sizes, int n_in,
                              void* d_out, int out_size)
{
    const float* xyz     = (const float*)d_in[0];
    const float* feature = (const float*)d_in[1];
    const int*   sidx    = (const int*)d_in[2];

    const float* w0  = (const float*)d_in[3];
    const float* b0  = (const float*)d_in[4];
    const float* g0  = (const float*)d_in[5];
    const float* bt0 = (const float*)d_in[6];
    const float* rm0 = (const float*)d_in[7];
    const float* rv0 = (const float*)d_in[8];
    const float* w1  = (const float*)d_in[9];
    const float* b1  = (const float*)d_in[10];
    const float* g1  = (const float*)d_in[11];
    const float* bt1 = (const float*)d_in[12];
    const float* rm1 = (const float*)d_in[13];
    const float* rv1 = (const float*)d_in[14];
    const float* w2  = (const float*)d_in[15];
    const float* b2  = (const float*)d_in[16];
    const float* g2  = (const float*)d_in[17];
    const float* bt2 = (const float*)d_in[18];
    const float* rm2 = (const float*)d_in[19];
    const float* rv2 = (const float*)d_in[20];

    float* out = (float*)d_out;

    prep_kernel<<<1, 256>>>(b0, g0, bt0, rm0, rv0,
                            b1, g1, bt1, rm1, rv1,
                            b2, g2, bt2, rm2, rv2);
    zero_kernel<<<(BB * NC + 255) / 256, 256>>>();
    count_kernel<<<(BB * NN + 255) / 256, 256>>>(xyz);
    scanB_kernel<<<BB * 32, 1024>>>();
    scanC_kernel<<<1, 128>>>();
    scanD_kernel<<<BB * 32, 1024>>>();
    scatter_kernel<<<(BB * NN + 255) / 256, 256>>>(xyz);
    knn_kernel<<<(BB * SS) / 8, 256>>>(xyz, sidx, out);
    mlp_kernel<<<(BB * SS) / 8, 256>>>(xyz, feature, sidx, w0, w1, w2, out);
}

// round 14
// speedup vs baseline: 2.8334x; 1.0007x over previous
#include <cuda_runtime.h>
#include <cstdint>

#define BB  4
#define NN  16384
#define SS  4096
#define KK  32
#define CINF 16
#define C0  19
#define C1  32
#define C2  32
#define C3  64
#define EPSF 1e-5f

// spatial grid
#define GG     32
#define NC     (GG * GG * GG)
#define BOUNDF 4.5f
#define HH     (9.0f / (float)GG)
#define MARGIN 1e-3f

#define FINF __int_as_float(0x7f800000)

// ---------------- scratch (no allocs allowed) ----------------
__device__ int    g_knn[BB * SS * KK];
__device__ float  g_a1[C1], g_b1[C1];
__device__ float  g_a2[C2], g_b2[C2];
__device__ float  g_a3[C3], g_b3[C3];

__device__ float4 g_pts[BB * NN];        // cell-sorted (x, y, z, ||p||^2)
__device__ int    g_pidx[BB * NN];       // in-batch original index
__device__ int    g_cell[BB * NN];       // cell id per original point
__device__ int    g_cnt[BB * NC];
__device__ int    g_cstart[BB * NC + 1];
__device__ int    g_ccur[BB * NC];
__device__ int    g_bsum[BB * 32];
__device__ int    g_boff[BB * 32];

// ---------------- packed f32x2 helpers (bitwise == two scalar fma.rn) --------
__device__ __forceinline__ unsigned long long packf2(float v)
{
    unsigned long long r;
    asm("mov.b64 %0, {%1, %1};" : "=l"(r) : "f"(v));
    return r;
}
__device__ __forceinline__ void fma2(unsigned long long& a,
                                     unsigned long long x, unsigned long long w)
{
    asm("fma.rn.f32x2 %0, %1, %2, %0;" : "+l"(a) : "l"(x), "l"(w));
}
__device__ __forceinline__ void unpack2(unsigned long long a, float& lo, float& hi)
{
    asm("mov.b64 {%0, %1}, %2;" : "=f"(lo), "=f"(hi) : "l"(a));
}

// ---------------- prep: fold BN as post-affine ----------------
__global__ void prep_kernel(
    const float* __restrict__ b0,
    const float* __restrict__ g0, const float* __restrict__ bt0,
    const float* __restrict__ rm0, const float* __restrict__ rv0,
    const float* __restrict__ b1,
    const float* __restrict__ g1, const float* __restrict__ bt1,
    const float* __restrict__ rm1, const float* __restrict__ rv1,
    const float* __restrict__ b2,
    const float* __restrict__ g2, const float* __restrict__ bt2,
    const float* __restrict__ rm2, const float* __restrict__ rv2)
{
    int t = threadIdx.x;
    if (t < C1) {
        float A = g0[t] * rsqrtf(rv0[t] + EPSF);
        g_a1[t] = A;
        g_b1[t] = (b0[t] - rm0[t]) * A + bt0[t];
    }
    if (t < C2) {
        float A = g1[t] * rsqrtf(rv1[t] + EPSF);
        g_a2[t] = A;
        g_b2[t] = (b1[t] - rm1[t]) * A + bt1[t];
    }
    if (t < C3) {
        float A = g2[t] * rsqrtf(rv2[t] + EPSF);
        g_a3[t] = A;
        g_b3[t] = (b2[t] - rm2[t]) * A + bt2[t];
    }
}

// ---------------- binning ----------------
__global__ void zero_kernel()
{
    int i = blockIdx.x * blockDim.x + threadIdx.x;
    if (i < BB * NC) g_cnt[i] = 0;
}

__device__ __forceinline__ int clampi(int v) { return min(GG - 1, max(0, v)); }

__device__ __forceinline__ int cell_of(float x, float y, float z)
{
    int cx = clampi((int)floorf((x + BOUNDF) * (1.0f / HH)));
    int cy = clampi((int)floorf((y + BOUNDF) * (1.0f / HH)));
    int cz = clampi((int)floorf((z + BOUNDF) * (1.0f / HH)));
    return (cx * GG + cy) * GG + cz;
}

__global__ void count_kernel(const float* __restrict__ xyz)
{
    int i = blockIdx.x * blockDim.x + threadIdx.x;
    if (i >= BB * NN) return;
    int b = i >> 14;
    const float* p = xyz + (size_t)i * 3;
    int cell = cell_of(p[0], p[1], p[2]);
    g_cell[i] = cell;
    atomicAdd(&g_cnt[b * NC + cell], 1);
}

// hierarchical scan: (B) per-block scans, (C) scan of block sums, (D) add
__global__ void scanB_kernel()   // grid = BB*32, block = 1024, 1 cell/thread
{
    __shared__ int wsum[32];
    const unsigned FULL = 0xffffffffu;
    int t = threadIdx.x, lane = t & 31, w = t >> 5;
    int b = blockIdx.x >> 5, blk = blockIdx.x & 31;
    int cell = blk * 1024 + t;
    int cnt = g_cnt[b * NC + cell];
    int v = cnt;
#pragma unroll
    for (int o = 1; o < 32; o <<= 1) {
        int u = __shfl_up_sync(FULL, v, o);
        if (lane >= o) v += u;
    }
    if (lane == 31) wsum[w] = v;
    __syncthreads();
    if (w == 0) {
        int s = wsum[lane];
#pragma unroll
        for (int o = 1; o < 32; o <<= 1) {
            int u = __shfl_up_sync(FULL, s, o);
            if (lane >= o) s += u;
        }
        wsum[lane] = s;
    }
    __syncthreads();
    int excl = v - cnt + ((w > 0) ? wsum[w - 1] : 0);
    g_cstart[b * NC + cell] = excl;                 // block-local for now
    if (t == 1023) g_bsum[blockIdx.x] = excl + cnt; // block total
}

__global__ void scanC_kernel()   // 1 block, 128 threads; warp w = batch w
{
    const unsigned FULL = 0xffffffffu;
    int lane = threadIdx.x & 31, w = threadIdx.x >> 5;
    int v = g_bsum[w * 32 + lane];
    int inc = v;
#pragma unroll
    for (int o = 1; o < 32; o <<= 1) {
        int u = __shfl_up_sync(FULL, inc, o);
        if (lane >= o) inc += u;
    }
    g_boff[w * 32 + lane] = inc - v + w * NN;
}

__global__ void scanD_kernel()   // grid = BB*32, block = 1024
{
    int b = blockIdx.x >> 5, blk = blockIdx.x & 31;
    int cell = blk * 1024 + threadIdx.x;
    int off = g_boff[blockIdx.x];
    int i = b * NC + cell;
    int v = g_cstart[i] + off;
    g_cstart[i] = v;
    g_ccur[i] = v;
    if (blockIdx.x == 0 && threadIdx.x == 0) g_cstart[BB * NC] = BB * NN;
}

__global__ void scatter_kernel(const float* __restrict__ xyz)
{
    int i = blockIdx.x * blockDim.x + threadIdx.x;
    if (i >= BB * NN) return;
    int b = i >> 14;
    int cell = g_cell[i];
    int pos = atomicAdd(&g_ccur[b * NC + cell], 1);
    const float* p = xyz + (size_t)i * 3;
    float x = p[0], y = p[1], z = p[2];
    float pp = __fadd_rn(__fadd_rn(__fmul_rn(x, x), __fmul_rn(y, y)),
                         __fmul_rn(z, z));
    g_pts[pos] = make_float4(x, y, z, pp);
    g_pidx[pos] = i & (NN - 1);
}

// ---------------- binned KNN v3: flattened group scans + bitonic init --------
// Distances bitwise-identical to R5..R12 (validated):
//   qq, pp : (x*x + y*y) + z*z, mul+add, NO fma
//   dot2   : fma(2qz,pz, fma(2qy,py, rn(2qx*px))) == 2*dot bitwise
//   d      : (qq - dot2) + pp, NO fma
// Warp-distributed sorted top-32 of (d, idx); order-independent result.
__device__ __forceinline__ bool lessdi(float d1, int i1, float d2, int i2)
{
    return (d1 < d2) || (d1 == d2 && i1 < i2);
}

// Scan a group of up to 32 per-lane segments [s0,e0), flattened so every
// chunk of 32 candidates fills all lanes. virgin: list untouched; first full
// chunk is bitonic-sorted straight into the distributed list.
__device__ void scan_group_flat(
    int s0, int e0, int lane, float qx2, float qy2, float qz2, float qq,
    float& kd, float& ld, int& li, bool& virgin)
{
    const unsigned FULL = 0xffffffffu;
    int len = max(e0 - s0, 0);
    int off = len;
#pragma unroll
    for (int o = 1; o < 32; o <<= 1) {
        int u = __shfl_up_sync(FULL, off, o);
        if (lane >= o) off += u;
    }
    int total = __shfl_sync(FULL, off, 31);
    off -= len;                                    // exclusive prefix

    for (int g0 = 0; g0 < total; g0 += 32) {
        int g = g0 + lane;
        bool v = g < total;
        // binary search: largest c with off[c] <= g (per-lane src shfl)
        int c = 0;
#pragma unroll
        for (int step = 16; step; step >>= 1) {
            int cand = c + step;
            int oc = __shfl_sync(FULL, off, cand);
            if (v && oc <= g) c = cand;
        }
        int sc = __shfl_sync(FULL, s0, c);
        int oc = __shfl_sync(FULL, off, c);
        float d = FINF;
        int ci = 0x7fffffff;
        if (v) {
            int jj = sc + (g - oc);
            float4 p = g_pts[jj];
            ci = g_pidx[jj];
            float dot2 = __fmaf_rn(qz2, p.z,
                         __fmaf_rn(qy2, p.y, __fmul_rn(qx2, p.x)));
            d = __fadd_rn(__fsub_rn(qq, dot2), p.w);
        }
        if (virgin && (total - g0 >= 32)) {
            // bitonic sort the full chunk ascending by (d, idx) -> the list
#pragma unroll
            for (int k = 2; k <= 32; k <<= 1) {
#pragma unroll
                for (int j = k >> 1; j > 0; j >>= 1) {
                    float d2 = __shfl_xor_sync(FULL, d, j);
                    int   i2 = __shfl_xor_sync(FULL, ci, j);
                    bool keepmin = (((lane & j) == 0) == ((lane & k) == 0));
                    bool pless = lessdi(d2, i2, d, ci);
                    if (keepmin == pless) { d = d2; ci = i2; }
                }
            }
            ld = d; li = ci;
            kd = __shfl_sync(FULL, ld, 31);
            virgin = false;
            continue;
        }
        unsigned m = __ballot_sync(FULL, v && d <= kd);
        if (m) {
            do {
                int src = __ffs(m) - 1;
                m &= m - 1;
                float cd = __shfl_sync(FULL, d, src);
                int   cc = __shfl_sync(FULL, ci, src);
                bool eb = lessdi(ld, li, cd, cc);
                int pos = __popc(__ballot_sync(FULL, eb));
                float sd = __shfl_up_sync(FULL, ld, 1);
                int   si = __shfl_up_sync(FULL, li, 1);
                if (lane == pos)      { ld = cd; li = cc; }
                else if (lane > pos)  { ld = sd; li = si; }
            } while (m);
            kd = __shfl_sync(FULL, ld, 31);
        }
        virgin = false;
    }
}

__global__ void __launch_bounds__(256)
knn_kernel(const float* __restrict__ xyz, const int* __restrict__ sidx,
           float* __restrict__ out)
{
    const unsigned FULL = 0xffffffffu;
    int warp = threadIdx.x >> 5;
    int lane = threadIdx.x & 31;
    int qid = blockIdx.x * 8 + warp;
    int b = qid >> 12;

    int sid = sidx[qid];
    const float* qp = xyz + ((size_t)b * NN + sid) * 3;
    float x = qp[0], y = qp[1], z = qp[2];
    float qq = __fadd_rn(__fadd_rn(__fmul_rn(x, x), __fmul_rn(y, y)),
                         __fmul_rn(z, z));
    float qx2 = 2.0f * x, qy2 = 2.0f * y, qz2 = 2.0f * z;

    if (lane == 0) {                                // fold meta outputs
        out[qid * 3 + 0] = x;
        out[qid * 3 + 1] = y;
        out[qid * 3 + 2] = z;
        out[(size_t)BB * SS * 3 + (size_t)BB * SS * C3 + qid] = (float)sid;
    }

    int cx = clampi((int)floorf((x + BOUNDF) * (1.0f / HH)));
    int cy = clampi((int)floorf((y + BOUNDF) * (1.0f / HH)));
    int cz = clampi((int)floorf((z + BOUNDF) * (1.0f / HH)));
    int cbase = b * NC;

    // ---- Phase A: pick starting radius (box count >= 48 or box = grid) ----
    int r = 1;
    for (;; r++) {
        bool full = (cx - r <= 0) && (cx + r >= GG - 1) &&
                    (cy - r <= 0) && (cy + r >= GG - 1) &&
                    (cz - r <= 0) && (cz + r >= GG - 1);
        int n = 2 * r + 1, nxy = n * n;
        int zlo = max(cz - r, 0), zhi = min(cz + r, GG - 1);
        int total = 0;
        for (int basec = 0; basec < nxy; basec += 32) {
            int idx = basec + lane;
            int cnt = 0;
            if (idx < nxy) {
                int xx = cx + idx / n - r, yy = cy + idx % n - r;
                if (xx >= 0 && xx < GG && yy >= 0 && yy < GG) {
                    int cid = cbase + (xx * GG + yy) * GG;
                    cnt = g_cstart[cid + zhi + 1] - g_cstart[cid + zlo];
                }
            }
#pragma unroll
            for (int o = 16; o; o >>= 1) cnt += __shfl_xor_sync(FULL, cnt, o);
            total += cnt;
        }
        if (total >= 48 || full) break;
    }

    float ld = FINF;
    int   li = 0x7fffffff;
    float kd = ld;
    bool  virgin = true;

    // ---- Phase B: flattened scan of the radius-r box ----
    {
        int n = 2 * r + 1, nxy = n * n;
        int zlo = max(cz - r, 0), zhi = min(cz + r, GG - 1);
        for (int basec = 0; basec < nxy; basec += 32) {
            int idx = basec + lane;
            int s0 = 0, e0 = 0;
            if (idx < nxy) {
                int xx = cx + idx / n - r, yy = cy + idx % n - r;
                if (xx >= 0 && xx < GG && yy >= 0 && yy < GG) {
                    int cid = cbase + (xx * GG + yy) * GG;
                    s0 = g_cstart[cid + zlo];
                    e0 = g_cstart[cid + zhi + 1];
                }
            }
            scan_group_flat(s0, e0, lane, qx2, qy2, qz2, qq, kd, ld, li, virgin);
        }
    }

    // ---- expand shells until safety bound holds ----
    for (;;) {
        bool full = (cx - r <= 0) && (cx + r >= GG - 1) &&
                    (cy - r <= 0) && (cy + r >= GG - 1) &&
                    (cz - r <= 0) && (cz + r >= GG - 1);
        float rb = (float)r * HH;
        if (full || kd < rb * rb - MARGIN) break;
        r++;
        int n = 2 * r + 1, nxy = n * n;
        int zlo = max(cz - r, 0), zhi = min(cz + r, GG - 1);
        for (int basec = 0; basec < nxy; basec += 32) {
            int idx = basec + lane;
            int s1 = 0, e1 = 0, s2 = 0, e2 = 0;
            if (idx < nxy) {
                int dx = idx / n - r, dy = idx % n - r;
                int xx = cx + dx, yy = cy + dy;
                if (xx >= 0 && xx < GG && yy >= 0 && yy < GG) {
                    int cid = cbase + (xx * GG + yy) * GG;
                    int adx = (dx < 0) ? -dx : dx, ady = (dy < 0) ? -dy : dy;
                    if (adx == r || ady == r) {          // new perimeter column
                        s1 = g_cstart[cid + zlo];
                        e1 = g_cstart[cid + zhi + 1];
                    } else {                              // two new z cells
                        int z1 = cz - r;
                        if (z1 >= 0) { s1 = g_cstart[cid + z1]; e1 = g_cstart[cid + z1 + 1]; }
                        int z2 = cz + r;
                        if (z2 < GG) { s2 = g_cstart[cid + z2]; e2 = g_cstart[cid + z2 + 1]; }
                    }
                }
            }
            scan_group_flat(s1, e1, lane, qx2, qy2, qz2, qq, kd, ld, li, virgin);
            scan_group_flat(s2, e2, lane, qx2, qy2, qz2, qq, kd, ld, li, virgin);
        }
    }

    g_knn[(size_t)qid * KK + lane] = li;
}

// ---------------- distributed warp max-reduce stage ----------------
template <int M, int SH>
__device__ __forceinline__ void redstage(float* o, int l)
{
    int bit = (l >> SH) & 1;
#pragma unroll
    for (int i = 0; i < M; i++) {
        float snd = bit ? o[i] : o[M + i];
        float rcv = __shfl_xor_sync(0xffffffffu, snd, 1 << SH);
        float mine = bit ? o[M + i] : o[i];
        o[i] = fmaxf(mine, rcv);
    }
}

// ---------------- MLP + maxpool: low-register channel passes ----------------
// fma.rn.f32x2 == two scalar fma.rn bitwise; per-channel c-order unchanged.
// Layer 3 done in two 32-channel halves, each max-pooled immediately via a
// 5-stage butterfly (per-channel max over lanes is order-free) so o[64] never
// lives in registers. Target <= 84 regs -> 3 blocks/SM (24 warps).
__global__ void __launch_bounds__(256, 3)
mlp_kernel(const float* __restrict__ xyz, const float* __restrict__ feat,
           const int* __restrict__ sidx,
           const float* __restrict__ w1g, const float* __restrict__ w2g,
           const float* __restrict__ w3g,
           float* __restrict__ out)
{
    __shared__ __align__(16) float sW1[C0 * C1];
    __shared__ __align__(16) float sW2[C1 * C2];
    __shared__ __align__(16) float sW3[C2 * C3];
    __shared__ float sA1[C1], sB1[C1], sA2[C2], sB2[C2], sA3[C3], sB3[C3];
    for (int i = threadIdx.x; i < C0 * C1; i += 256) sW1[i] = w1g[i];
    for (int i = threadIdx.x; i < C1 * C2; i += 256) sW2[i] = w2g[i];
    for (int i = threadIdx.x; i < C2 * C3; i += 256) sW3[i] = w3g[i];
    if (threadIdx.x < C1) { sA1[threadIdx.x] = g_a1[threadIdx.x]; sB1[threadIdx.x] = g_b1[threadIdx.x]; }
    if (threadIdx.x < C2) { sA2[threadIdx.x] = g_a2[threadIdx.x]; sB2[threadIdx.x] = g_b2[threadIdx.x]; }
    if (threadIdx.x < C3) { sA3[threadIdx.x] = g_a3[threadIdx.x]; sB3[threadIdx.x] = g_b3[threadIdx.x]; }
    __syncthreads();

    int warp = threadIdx.x >> 5;
    int lane = threadIdx.x & 31;
    int qid = blockIdx.x * 8 + warp;
    int b = qid >> 12;

    int sid = sidx[qid];
    const float* qp = xyz + ((size_t)b * NN + sid) * 3;
    float qx = qp[0], qy = qp[1], qz = qp[2];

    int nb = g_knn[(size_t)qid * KK + lane];
    const float* pp = xyz + ((size_t)b * NN + nb) * 3;

    float x[C0];
    x[0] = pp[0] - qx;
    x[1] = pp[1] - qy;
    x[2] = pp[2] - qz;
    const float4* f4 = (const float4*)(feat + ((size_t)b * NN + nb) * CINF);
#pragma unroll
    for (int v = 0; v < 4; v++) {
        float4 fv = f4[v];
        x[3 + 4 * v] = fv.x; x[4 + 4 * v] = fv.y;
        x[5 + 4 * v] = fv.z; x[6 + 4 * v] = fv.w;
    }

    // layer 1: 19 -> 32 (single pass, 16 packed accumulators)
    float y[C1];
    {
        unsigned long long a1[C1 / 2];
#pragma unroll
        for (int j = 0; j < C1 / 2; j++) a1[j] = 0ull;
        const ulonglong2* Wv = (const ulonglong2*)sW1;
#pragma unroll
        for (int c = 0; c < C0; c++) {
            unsigned long long xp = packf2(x[c]);
#pragma unroll
            for (int q = 0; q < C1 / 4; q++) {
                ulonglong2 wv = Wv[c * (C1 / 4) + q];
                fma2(a1[2 * q + 0], xp, wv.x);
                fma2(a1[2 * q + 1], xp, wv.y);
            }
        }
#pragma unroll
        for (int j = 0; j < C1 / 2; j++) unpack2(a1[j], y[2 * j], y[2 * j + 1]);
    }
#pragma unroll
    for (int d = 0; d < C1; d++)
        y[d] = fmaxf(fmaf(y[d], sA1[d], sB1[d]), 0.0f);

    // layer 2: 32 -> 32 (single pass)
    float z[C2];
    {
        unsigned long long a2[C2 / 2];
#pragma unroll
        for (int j = 0; j < C2 / 2; j++) a2[j] = 0ull;
        const ulonglong2* Wv = (const ulonglong2*)sW2;
#pragma unroll
        for (int c = 0; c < C1; c++) {
            unsigned long long xp = packf2(y[c]);
#pragma unroll
            for (int q = 0; q < C2 / 4; q++) {
                ulonglong2 wv = Wv[c * (C2 / 4) + q];
                fma2(a2[2 * q + 0], xp, wv.x);
                fma2(a2[2 * q + 1], xp, wv.y);
            }
        }
#pragma unroll
        for (int j = 0; j < C2 / 2; j++) unpack2(a2[j], z[2 * j], z[2 * j + 1]);
    }
#pragma unroll
    for (int d = 0; d < C2; d++)
        z[d] = fmaxf(fmaf(z[d], sA2[d], sB2[d]), 0.0f);

    // layer 3: 32 -> 64 in two 32-channel halves, each pooled immediately.
    // ch = bitrev5(lane) after the 5-stage butterfly (1 channel per lane).
    const ulonglong2* Wv3 = (const ulonglong2*)sW3;   // 16 ulonglong2 per row
    int chb = (((lane >> 0) & 1) << 4) | (((lane >> 1) & 1) << 3) |
              (((lane >> 2) & 1) << 2) | (((lane >> 3) & 1) << 1) |
              (((lane >> 4) & 1) << 0);
    float* obase = out + (size_t)BB * SS * 3 + (size_t)qid * C3;
#pragma unroll
    for (int half = 0; half < 2; half++) {
        float oh[32];
        {
            unsigned long long a3[16];
#pragma unroll
            for (int j = 0; j < 16; j++) a3[j] = 0ull;
#pragma unroll
            for (int c = 0; c < C2; c++) {
                unsigned long long xp = packf2(z[c]);
#pragma unroll
                for (int q = 0; q < 8; q++) {
                    ulonglong2 wv = Wv3[c * 16 + half * 8 + q];
                    fma2(a3[2 * q + 0], xp, wv.x);
                    fma2(a3[2 * q + 1], xp, wv.y);
                }
            }
#pragma unroll
            for (int j = 0; j < 16; j++) unpack2(a3[j], oh[2 * j], oh[2 * j + 1]);
        }
#pragma unroll
        for (int d = 0; d < 32; d++) {
            int dc = half * 32 + d;
            oh[d] = fmaxf(fmaf(oh[d], sA3[dc], sB3[dc]), 0.0f);
        }
        // pool this half: 32 channels -> 1 channel per lane
        redstage<16, 0>(oh, lane);
        redstage<8,  1>(oh, lane);
        redstage<4,  2>(oh, lane);
        redstage<2,  3>(oh, lane);
        redstage<1,  4>(oh, lane);
        obase[half * 32 + chb] = oh[0];
    }
}

// ---------------- launch ----------------
extern "C" void kernel_launch(void* const* d_in, const int* in_sizes, int n_in,
                              void* d_out, int out_size)
{
    const float* xyz     = (const float*)d_in[0];
    const float* feature = (const float*)d_in[1];
    const int*   sidx    = (const int*)d_in[2];

    const float* w0  = (const float*)d_in[3];
    const float* b0  = (const float*)d_in[4];
    const float* g0  = (const float*)d_in[5];
    const float* bt0 = (const float*)d_in[6];
    const float* rm0 = (const float*)d_in[7];
    const float* rv0 = (const float*)d_in[8];
    const float* w1  = (const float*)d_in[9];
    const float* b1  = (const float*)d_in[10];
    const float* g1  = (const float*)d_in[11];
    const float* bt1 = (const float*)d_in[12];
    const float* rm1 = (const float*)d_in[13];
    const float* rv1 = (const float*)d_in[14];
    const float* w2  = (const float*)d_in[15];
    const float* b2  = (const float*)d_in[16];
    const float* g2  = (const float*)d_in[17];
    const float* bt2 = (const float*)d_in[18];
    const float* rm2 = (const float*)d_in[19];
    const float* rv2 = (const float*)d_in[20];

    float* out = (float*)d_out;

    prep_kernel<<<1, 256>>>(b0, g0, bt0, rm0, rv0,
                            b1, g1, bt1, rm1, rv1,
                            b2, g2, bt2, rm2, rv2);
    zero_kernel<<<(BB * NC + 255) / 256, 256>>>();
    count_kernel<<<(BB * NN + 255) / 256, 256>>>(xyz);
    scanB_kernel<<<BB * 32, 1024>>>();
    scanC_kernel<<<1, 128>>>();
    scanD_kernel<<<BB * 32, 1024>>>();
    scatter_kernel<<<(BB * NN + 255) / 256, 256>>>(xyz);
    knn_kernel<<<(BB * SS) / 8, 256>>>(xyz, sidx, out);
    mlp_kernel<<<(BB * SS) / 8, 256>>>(xyz, feature, sidx, w0, w1, w2, out);
}

// round 15
// speedup vs baseline: 3.0313x; 1.0698x over previous
#include <cuda_runtime.h>
#include <cstdint>

#define BB  4
#define NN  16384
#define SS  4096
#define KK  32
#define CINF 16
#define C0  19
#define C1  32
#define C2  32
#define C3  64
#define EPSF 1e-5f

// spatial grid
#define GG     32
#define NC     (GG * GG * GG)
#define BOUNDF 4.5f
#define HH     (9.0f / (float)GG)
#define MARGIN 1e-3f

#define FINF __int_as_float(0x7f800000)

// ---------------- scratch (no allocs allowed) ----------------
__device__ int    g_knn[BB * SS * KK];
__device__ float  g_a1[C1], g_b1[C1];
__device__ float  g_a2[C2], g_b2[C2];
__device__ float  g_a3[C3], g_b3[C3];

__device__ float4 g_pts[BB * NN];        // cell-sorted (x, y, z, ||p||^2)
__device__ int    g_pidx[BB * NN];       // in-batch original index
__device__ int    g_cell[BB * NN];       // cell id per original point
__device__ int    g_cnt[BB * NC];
__device__ int    g_cstart[BB * NC + 1];
__device__ int    g_ccur[BB * NC];
__device__ int    g_bsum[BB * 32];
__device__ int    g_boff[BB * 32];

// ---------------- packed f32x2 helpers (bitwise == two scalar fma.rn) --------
__device__ __forceinline__ unsigned long long packf2(float v)
{
    unsigned long long r;
    asm("mov.b64 %0, {%1, %1};" : "=l"(r) : "f"(v));
    return r;
}
__device__ __forceinline__ void fma2(unsigned long long& a,
                                     unsigned long long x, unsigned long long w)
{
    asm("fma.rn.f32x2 %0, %1, %2, %0;" : "+l"(a) : "l"(x), "l"(w));
}
__device__ __forceinline__ void unpack2(unsigned long long a, float& lo, float& hi)
{
    asm("mov.b64 {%0, %1}, %2;" : "=f"(lo), "=f"(hi) : "l"(a));
}

// ---------------- prep: fold BN as post-affine ----------------
__global__ void prep_kernel(
    const float* __restrict__ b0,
    const float* __restrict__ g0, const float* __restrict__ bt0,
    const float* __restrict__ rm0, const float* __restrict__ rv0,
    const float* __restrict__ b1,
    const float* __restrict__ g1, const float* __restrict__ bt1,
    const float* __restrict__ rm1, const float* __restrict__ rv1,
    const float* __restrict__ b2,
    const float* __restrict__ g2, const float* __restrict__ bt2,
    const float* __restrict__ rm2, const float* __restrict__ rv2)
{
    int t = threadIdx.x;
    if (t < C1) {
        float A = g0[t] * rsqrtf(rv0[t] + EPSF);
        g_a1[t] = A;
        g_b1[t] = (b0[t] - rm0[t]) * A + bt0[t];
    }
    if (t < C2) {
        float A = g1[t] * rsqrtf(rv1[t] + EPSF);
        g_a2[t] = A;
        g_b2[t] = (b1[t] - rm1[t]) * A + bt1[t];
    }
    if (t < C3) {
        float A = g2[t] * rsqrtf(rv2[t] + EPSF);
        g_a3[t] = A;
        g_b3[t] = (b2[t] - rm2[t]) * A + bt2[t];
    }
}

// ---------------- binning ----------------
__global__ void zero_kernel()
{
    int i = blockIdx.x * blockDim.x + threadIdx.x;
    if (i < BB * NC) g_cnt[i] = 0;
}

__device__ __forceinline__ int clampi(int v) { return min(GG - 1, max(0, v)); }

__device__ __forceinline__ int cell_of(float x, float y, float z)
{
    int cx = clampi((int)floorf((x + BOUNDF) * (1.0f / HH)));
    int cy = clampi((int)floorf((y + BOUNDF) * (1.0f / HH)));
    int cz = clampi((int)floorf((z + BOUNDF) * (1.0f / HH)));
    return (cx * GG + cy) * GG + cz;
}

__global__ void count_kernel(const float* __restrict__ xyz)
{
    int i = blockIdx.x * blockDim.x + threadIdx.x;
    if (i >= BB * NN) return;
    int b = i >> 14;
    const float* p = xyz + (size_t)i * 3;
    int cell = cell_of(p[0], p[1], p[2]);
    g_cell[i] = cell;
    atomicAdd(&g_cnt[b * NC + cell], 1);
}

// hierarchical scan: (B) per-block scans, (C) scan of block sums, (D) add
__global__ void scanB_kernel()   // grid = BB*32, block = 1024, 1 cell/thread
{
    __shared__ int wsum[32];
    const unsigned FULL = 0xffffffffu;
    int t = threadIdx.x, lane = t & 31, w = t >> 5;
    int b = blockIdx.x >> 5, blk = blockIdx.x & 31;
    int cell = blk * 1024 + t;
    int cnt = g_cnt[b * NC + cell];
    int v = cnt;
#pragma unroll
    for (int o = 1; o < 32; o <<= 1) {
        int u = __shfl_up_sync(FULL, v, o);
        if (lane >= o) v += u;
    }
    if (lane == 31) wsum[w] = v;
    __syncthreads();
    if (w == 0) {
        int s = wsum[lane];
#pragma unroll
        for (int o = 1; o < 32; o <<= 1) {
            int u = __shfl_up_sync(FULL, s, o);
            if (lane >= o) s += u;
        }
        wsum[lane] = s;
    }
    __syncthreads();
    int excl = v - cnt + ((w > 0) ? wsum[w - 1] : 0);
    g_cstart[b * NC + cell] = excl;                 // block-local for now
    if (t == 1023) g_bsum[blockIdx.x] = excl + cnt; // block total
}

__global__ void scanC_kernel()   // 1 block, 128 threads; warp w = batch w
{
    const unsigned FULL = 0xffffffffu;
    int lane = threadIdx.x & 31, w = threadIdx.x >> 5;
    int v = g_bsum[w * 32 + lane];
    int inc = v;
#pragma unroll
    for (int o = 1; o < 32; o <<= 1) {
        int u = __shfl_up_sync(FULL, inc, o);
        if (lane >= o) inc += u;
    }
    g_boff[w * 32 + lane] = inc - v + w * NN;
}

__global__ void scanD_kernel()   // grid = BB*32, block = 1024
{
    int b = blockIdx.x >> 5, blk = blockIdx.x & 31;
    int cell = blk * 1024 + threadIdx.x;
    int off = g_boff[blockIdx.x];
    int i = b * NC + cell;
    int v = g_cstart[i] + off;
    g_cstart[i] = v;
    g_ccur[i] = v;
    if (blockIdx.x == 0 && threadIdx.x == 0) g_cstart[BB * NC] = BB * NN;
}

__global__ void scatter_kernel(const float* __restrict__ xyz)
{
    int i = blockIdx.x * blockDim.x + threadIdx.x;
    if (i >= BB * NN) return;
    int b = i >> 14;
    int cell = g_cell[i];
    int pos = atomicAdd(&g_ccur[b * NC + cell], 1);
    const float* p = xyz + (size_t)i * 3;
    float x = p[0], y = p[1], z = p[2];
    float pp = __fadd_rn(__fadd_rn(__fmul_rn(x, x), __fmul_rn(y, y)),
                         __fmul_rn(z, z));
    g_pts[pos] = make_float4(x, y, z, pp);
    g_pidx[pos] = i & (NN - 1);
}

// ---------------- binned KNN v4: flattened scans + bitonic init + merge ------
// Distances bitwise-identical to R5..R14 (validated):
//   qq, pp : (x*x + y*y) + z*z, mul+add, NO fma
//   dot2   : fma(2qz,pz, fma(2qy,py, rn(2qx*px))) == 2*dot bitwise
//   d      : (qq - dot2) + pp, NO fma
// Warp-distributed sorted top-32 of (d, idx); order-independent exact result.
__device__ __forceinline__ bool lessdi(float d1, int i1, float d2, int i2)
{
    return (d1 < d2) || (d1 == d2 && i1 < i2);
}

// full ascending bitonic sort of (d, ci) across 32 lanes (lex order)
__device__ __forceinline__ void bitonic32(float& d, int& ci, int lane)
{
    const unsigned FULL = 0xffffffffu;
#pragma unroll
    for (int k = 2; k <= 32; k <<= 1) {
#pragma unroll
        for (int j = k >> 1; j > 0; j >>= 1) {
            float d2 = __shfl_xor_sync(FULL, d, j);
            int   i2 = __shfl_xor_sync(FULL, ci, j);
            bool keepmin = (((lane & j) == 0) == ((lane & k) == 0));
            bool pless = lessdi(d2, i2, d, ci);
            if (keepmin == pless) { d = d2; ci = i2; }
        }
    }
}

// Scan a group of up to 32 per-lane segments [s0,e0), flattened so every
// chunk of 32 candidates fills all lanes. virgin: list untouched; first full
// chunk is bitonic-sorted straight into the distributed list. Chunks with
// many survivors use an exact sorted-merge network instead of per-candidate
// insertion (top-32 of the union of two sorted 32-lists).
__device__ void scan_group_flat(
    int s0, int e0, int lane, float qx2, float qy2, float qz2, float qq,
    float& kd, float& ld, int& li, bool& virgin)
{
    const unsigned FULL = 0xffffffffu;
    int len = max(e0 - s0, 0);
    int off = len;
#pragma unroll
    for (int o = 1; o < 32; o <<= 1) {
        int u = __shfl_up_sync(FULL, off, o);
        if (lane >= o) off += u;
    }
    int total = __shfl_sync(FULL, off, 31);
    off -= len;                                    // exclusive prefix

    for (int g0 = 0; g0 < total; g0 += 32) {
        int g = g0 + lane;
        bool v = g < total;
        // binary search: largest c with off[c] <= g (per-lane src shfl)
        int c = 0;
#pragma unroll
        for (int step = 16; step; step >>= 1) {
            int cand = c + step;
            int oc = __shfl_sync(FULL, off, cand);
            if (v && oc <= g) c = cand;
        }
        int sc = __shfl_sync(FULL, s0, c);
        int oc = __shfl_sync(FULL, off, c);
        float d = FINF;
        int ci = 0x7fffffff;
        if (v) {
            int jj = sc + (g - oc);
            float4 p = g_pts[jj];
            ci = g_pidx[jj];
            float dot2 = __fmaf_rn(qz2, p.z,
                         __fmaf_rn(qy2, p.y, __fmul_rn(qx2, p.x)));
            d = __fadd_rn(__fsub_rn(qq, dot2), p.w);
        }
        if (virgin && (total - g0 >= 32)) {
            // bitonic sort the full chunk ascending -> becomes the list
            bitonic32(d, ci, lane);
            ld = d; li = ci;
            kd = __shfl_sync(FULL, ld, 31);
            virgin = false;
            continue;
        }
        unsigned m = __ballot_sync(FULL, v && d <= kd);
        int cnt = __popc(m);
        if (cnt >= 6) {
            // exact merge: sort survivors (losers = +inf), pair against the
            // reversed list (C[i] = min(list[i], cand[31-i]) holds the 32
            // smallest of the union, bitonic), then 5-stage clean.
            bool keep = v && d <= kd;
            float cd = keep ? d : FINF;
            int   cc = keep ? ci : 0x7fffffff;
            bitonic32(cd, cc, lane);
            float rd = __shfl_sync(FULL, cd, 31 - lane);
            int   ri = __shfl_sync(FULL, cc, 31 - lane);
            bool take = lessdi(rd, ri, ld, li);
            float nd = take ? rd : ld;
            int   ni = take ? ri : li;
#pragma unroll
            for (int j = 16; j > 0; j >>= 1) {
                float d2 = __shfl_xor_sync(FULL, nd, j);
                int   i2 = __shfl_xor_sync(FULL, ni, j);
                bool keepmin = ((lane & j) == 0);
                bool pless = lessdi(d2, i2, nd, ni);
                if (keepmin == pless) { nd = d2; ni = i2; }
            }
            ld = nd; li = ni;
            kd = __shfl_sync(FULL, ld, 31);
        } else if (m) {
            do {
                int src = __ffs(m) - 1;
                m &= m - 1;
                float cd = __shfl_sync(FULL, d, src);
                int   cc = __shfl_sync(FULL, ci, src);
                bool eb = lessdi(ld, li, cd, cc);
                int pos = __popc(__ballot_sync(FULL, eb));
                float sd = __shfl_up_sync(FULL, ld, 1);
                int   si = __shfl_up_sync(FULL, li, 1);
                if (lane == pos)      { ld = cd; li = cc; }
                else if (lane > pos)  { ld = sd; li = si; }
            } while (m);
            kd = __shfl_sync(FULL, ld, 31);
        }
        virgin = false;
    }
}

__global__ void __launch_bounds__(256)
knn_kernel(const float* __restrict__ xyz, const int* __restrict__ sidx,
           float* __restrict__ out)
{
    const unsigned FULL = 0xffffffffu;
    int warp = threadIdx.x >> 5;
    int lane = threadIdx.x & 31;
    int qid = blockIdx.x * 8 + warp;
    int b = qid >> 12;

    int sid = sidx[qid];
    const float* qp = xyz + ((size_t)b * NN + sid) * 3;
    float x = qp[0], y = qp[1], z = qp[2];
    float qq = __fadd_rn(__fadd_rn(__fmul_rn(x, x), __fmul_rn(y, y)),
                         __fmul_rn(z, z));
    float qx2 = 2.0f * x, qy2 = 2.0f * y, qz2 = 2.0f * z;

    if (lane == 0) {                                // fold meta outputs
        out[qid * 3 + 0] = x;
        out[qid * 3 + 1] = y;
        out[qid * 3 + 2] = z;
        out[(size_t)BB * SS * 3 + (size_t)BB * SS * C3 + qid] = (float)sid;
    }

    int cx = clampi((int)floorf((x + BOUNDF) * (1.0f / HH)));
    int cy = clampi((int)floorf((y + BOUNDF) * (1.0f / HH)));
    int cz = clampi((int)floorf((z + BOUNDF) * (1.0f / HH)));
    int cbase = b * NC;

    // ---- Phase A: pick starting radius (box count >= 48 or box = grid) ----
    int r = 1;
    for (;; r++) {
        bool full = (cx - r <= 0) && (cx + r >= GG - 1) &&
                    (cy - r <= 0) && (cy + r >= GG - 1) &&
                    (cz - r <= 0) && (cz + r >= GG - 1);
        int n = 2 * r + 1, nxy = n * n;
        int zlo = max(cz - r, 0), zhi = min(cz + r, GG - 1);
        int total = 0;
        for (int basec = 0; basec < nxy; basec += 32) {
            int idx = basec + lane;
            int cnt = 0;
            if (idx < nxy) {
                int xx = cx + idx / n - r, yy = cy + idx % n - r;
                if (xx >= 0 && xx < GG && yy >= 0 && yy < GG) {
                    int cid = cbase + (xx * GG + yy) * GG;
                    cnt = g_cstart[cid + zhi + 1] - g_cstart[cid + zlo];
                }
            }
#pragma unroll
            for (int o = 16; o; o >>= 1) cnt += __shfl_xor_sync(FULL, cnt, o);
            total += cnt;
        }
        if (total >= 48 || full) break;
    }

    float ld = FINF;
    int   li = 0x7fffffff;
    float kd = ld;
    bool  virgin = true;

    // ---- Phase B: flattened scan of the radius-r box ----
    {
        int n = 2 * r + 1, nxy = n * n;
        int zlo = max(cz - r, 0), zhi = min(cz + r, GG - 1);
        for (int basec = 0; basec < nxy; basec += 32) {
            int idx = basec + lane;
            int s0 = 0, e0 = 0;
            if (idx < nxy) {
                int xx = cx + idx / n - r, yy = cy + idx % n - r;
                if (xx >= 0 && xx < GG && yy >= 0 && yy < GG) {
                    int cid = cbase + (xx * GG + yy) * GG;
                    s0 = g_cstart[cid + zlo];
                    e0 = g_cstart[cid + zhi + 1];
                }
            }
            scan_group_flat(s0, e0, lane, qx2, qy2, qz2, qq, kd, ld, li, virgin);
        }
    }

    // ---- expand shells until safety bound holds ----
    for (;;) {
        bool full = (cx - r <= 0) && (cx + r >= GG - 1) &&
                    (cy - r <= 0) && (cy + r >= GG - 1) &&
                    (cz - r <= 0) && (cz + r >= GG - 1);
        float rb = (float)r * HH;
        if (full || kd < rb * rb - MARGIN) break;
        r++;
        int n = 2 * r + 1, nxy = n * n;
        int zlo = max(cz - r, 0), zhi = min(cz + r, GG - 1);
        for (int basec = 0; basec < nxy; basec += 32) {
            int idx = basec + lane;
            int s1 = 0, e1 = 0, s2 = 0, e2 = 0;
            if (idx < nxy) {
                int dx = idx / n - r, dy = idx % n - r;
                int xx = cx + dx, yy = cy + dy;
                if (xx >= 0 && xx < GG && yy >= 0 && yy < GG) {
                    int cid = cbase + (xx * GG + yy) * GG;
                    int adx = (dx < 0) ? -dx : dx, ady = (dy < 0) ? -dy : dy;
                    if (adx == r || ady == r) {          // new perimeter column
                        s1 = g_cstart[cid + zlo];
                        e1 = g_cstart[cid + zhi + 1];
                    } else {                              // two new z cells
                        int z1 = cz - r;
                        if (z1 >= 0) { s1 = g_cstart[cid + z1]; e1 = g_cstart[cid + z1 + 1]; }
                        int z2 = cz + r;
                        if (z2 < GG) { s2 = g_cstart[cid + z2]; e2 = g_cstart[cid + z2 + 1]; }
                    }
                }
            }
            scan_group_flat(s1, e1, lane, qx2, qy2, qz2, qq, kd, ld, li, virgin);
            scan_group_flat(s2, e2, lane, qx2, qy2, qz2, qq, kd, ld, li, virgin);
        }
    }

    g_knn[(size_t)qid * KK + lane] = li;
}

// ---------------- distributed warp max-reduce stage ----------------
template <int M, int SH>
__device__ __forceinline__ void redstage(float* o, int l)
{
    int bit = (l >> SH) & 1;
#pragma unroll
    for (int i = 0; i < M; i++) {
        float snd = bit ? o[i] : o[M + i];
        float rcv = __shfl_xor_sync(0xffffffffu, snd, 1 << SH);
        float mine = bit ? o[M + i] : o[i];
        o[i] = fmaxf(mine, rcv);
    }
}

// ---------------- MLP + maxpool (unchanged from R14) ----------------
__global__ void __launch_bounds__(256, 3)
mlp_kernel(const float* __restrict__ xyz, const float* __restrict__ feat,
           const int* __restrict__ sidx,
           const float* __restrict__ w1g, const float* __restrict__ w2g,
           const float* __restrict__ w3g,
           float* __restrict__ out)
{
    __shared__ __align__(16) float sW1[C0 * C1];
    __shared__ __align__(16) float sW2[C1 * C2];
    __shared__ __align__(16) float sW3[C2 * C3];
    __shared__ float sA1[C1], sB1[C1], sA2[C2], sB2[C2], sA3[C3], sB3[C3];
    for (int i = threadIdx.x; i < C0 * C1; i += 256) sW1[i] = w1g[i];
    for (int i = threadIdx.x; i < C1 * C2; i += 256) sW2[i] = w2g[i];
    for (int i = threadIdx.x; i < C2 * C3; i += 256) sW3[i] = w3g[i];
    if (threadIdx.x < C1) { sA1[threadIdx.x] = g_a1[threadIdx.x]; sB1[threadIdx.x] = g_b1[threadIdx.x]; }
    if (threadIdx.x < C2) { sA2[threadIdx.x] = g_a2[threadIdx.x]; sB2[threadIdx.x] = g_b2[threadIdx.x]; }
    if (threadIdx.x < C3) { sA3[threadIdx.x] = g_a3[threadIdx.x]; sB3[threadIdx.x] = g_b3[threadIdx.x]; }
    __syncthreads();

    int warp = threadIdx.x >> 5;
    int lane = threadIdx.x & 31;
    int qid = blockIdx.x * 8 + warp;
    int b = qid >> 12;

    int sid = sidx[qid];
    const float* qp = xyz + ((size_t)b * NN + sid) * 3;
    float qx = qp[0], qy = qp[1], qz = qp[2];

    int nb = g_knn[(size_t)qid * KK + lane];
    const float* pp = xyz + ((size_t)b * NN + nb) * 3;

    float x[C0];
    x[0] = pp[0] - qx;
    x[1] = pp[1] - qy;
    x[2] = pp[2] - qz;
    const float4* f4 = (const float4*)(feat + ((size_t)b * NN + nb) * CINF);
#pragma unroll
    for (int v = 0; v < 4; v++) {
        float4 fv = f4[v];
        x[3 + 4 * v] = fv.x; x[4 + 4 * v] = fv.y;
        x[5 + 4 * v] = fv.z; x[6 + 4 * v] = fv.w;
    }

    // layer 1: 19 -> 32 (single pass, 16 packed accumulators)
    float y[C1];
    {
        unsigned long long a1[C1 / 2];
#pragma unroll
        for (int j = 0; j < C1 / 2; j++) a1[j] = 0ull;
        const ulonglong2* Wv = (const ulonglong2*)sW1;
#pragma unroll
        for (int c = 0; c < C0; c++) {
            unsigned long long xp = packf2(x[c]);
#pragma unroll
            for (int q = 0; q < C1 / 4; q++) {
                ulonglong2 wv = Wv[c * (C1 / 4) + q];
                fma2(a1[2 * q + 0], xp, wv.x);
                fma2(a1[2 * q + 1], xp, wv.y);
            }
        }
#pragma unroll
        for (int j = 0; j < C1 / 2; j++) unpack2(a1[j], y[2 * j], y[2 * j + 1]);
    }
#pragma unroll
    for (int d = 0; d < C1; d++)
        y[d] = fmaxf(fmaf(y[d], sA1[d], sB1[d]), 0.0f);

    // layer 2: 32 -> 32 (single pass)
    float z[C2];
    {
        unsigned long long a2[C2 / 2];
#pragma unroll
        for (int j = 0; j < C2 / 2; j++) a2[j] = 0ull;
        const ulonglong2* Wv = (const ulonglong2*)sW2;
#pragma unroll
        for (int c = 0; c < C1; c++) {
            unsigned long long xp = packf2(y[c]);
#pragma unroll
            for (int q = 0; q < C2 / 4; q++) {
                ulonglong2 wv = Wv[c * (C2 / 4) + q];
                fma2(a2[2 * q + 0], xp, wv.x);
                fma2(a2[2 * q + 1], xp, wv.y);
            }
        }
#pragma unroll
        for (int j = 0; j < C2 / 2; j++) unpack2(a2[j], z[2 * j], z[2 * j + 1]);
    }
#pragma unroll
    for (int d = 0; d < C2; d++)
        z[d] = fmaxf(fmaf(z[d], sA2[d], sB2[d]), 0.0f);

    // layer 3: 32 -> 64 in two 32-channel halves, each pooled immediately.
    const ulonglong2* Wv3 = (const ulonglong2*)sW3;   // 16 ulonglong2 per row
    int chb = (((lane >> 0) & 1) << 4) | (((lane >> 1) & 1) << 3) |
              (((lane >> 2) & 1) << 2) | (((lane >> 3) & 1) << 1) |
              (((lane >> 4) & 1) << 0);
    float* obase = out + (size_t)BB * SS * 3 + (size_t)qid * C3;
#pragma unroll
    for (int half = 0; half < 2; half++) {
        float oh[32];
        {
            unsigned long long a3[16];
#pragma unroll
            for (int j = 0; j < 16; j++) a3[j] = 0ull;
#pragma unroll
            for (int c = 0; c < C2; c++) {
                unsigned long long xp = packf2(z[c]);
#pragma unroll
                for (int q = 0; q < 8; q++) {
                    ulonglong2 wv = Wv3[c * 16 + half * 8 + q];
                    fma2(a3[2 * q + 0], xp, wv.x);
                    fma2(a3[2 * q + 1], xp, wv.y);
                }
            }
#pragma unroll
            for (int j = 0; j < 16; j++) unpack2(a3[j], oh[2 * j], oh[2 * j + 1]);
        }
#pragma unroll
        for (int d = 0; d < 32; d++) {
            int dc = half * 32 + d;
            oh[d] = fmaxf(fmaf(oh[d], sA3[dc], sB3[dc]), 0.0f);
        }
        // pool this half: 32 channels -> 1 channel per lane
        redstage<16, 0>(oh, lane);
        redstage<8,  1>(oh, lane);
        redstage<4,  2>(oh, lane);
        redstage<2,  3>(oh, lane);
        redstage<1,  4>(oh, lane);
        obase[half * 32 + chb] = oh[0];
    }
}

// ---------------- launch ----------------
extern "C" void kernel_launch(void* const* d_in, const int* in_sizes, int n_in,
                              void* d_out, int out_size)
{
    const float* xyz     = (const float*)d_in[0];
    const float* feature = (const float*)d_in[1];
    const int*   sidx    = (const int*)d_in[2];

    const float* w0  = (const float*)d_in[3];
    const float* b0  = (const float*)d_in[4];
    const float* g0  = (const float*)d_in[5];
    const float* bt0 = (const float*)d_in[6];
    const float* rm0 = (const float*)d_in[7];
    const float* rv0 = (const float*)d_in[8];
    const float* w1  = (const float*)d_in[9];
    const float* b1  = (const float*)d_in[10];
    const float* g1  = (const float*)d_in[11];
    const float* bt1 = (const float*)d_in[12];
    const float* rm1 = (const float*)d_in[13];
    const float* rv1 = (const float*)d_in[14];
    const float* w2  = (const float*)d_in[15];
    const float* b2  = (const float*)d_in[16];
    const float* g2  = (const float*)d_in[17];
    const float* bt2 = (const float*)d_in[18];
    const float* rm2 = (const float*)d_in[19];
    const float* rv2 = (const float*)d_in[20];

    float* out = (float*)d_out;

    prep_kernel<<<1, 256>>>(b0, g0, bt0, rm0, rv0,
                            b1, g1, bt1, rm1, rv1,
                            b2, g2, bt2, rm2, rv2);
    zero_kernel<<<(BB * NC + 255) / 256, 256>>>();
    count_kernel<<<(BB * NN + 255) / 256, 256>>>(xyz);
    scanB_kernel<<<BB * 32, 1024>>>();
    scanC_kernel<<<1, 128>>>();
    scanD_kernel<<<BB * 32, 1024>>>();
    scatter_kernel<<<(BB * NN + 255) / 256, 256>>>(xyz);
    knn_kernel<<<(BB * SS) / 8, 256>>>(xyz, sidx, out);
    mlp_kernel<<<(BB * SS) / 8, 256>>>(xyz, feature, sidx, w0, w1, w2, out);
}